// round 1
// baseline (speedup 1.0000x reference)
#include <cuda_runtime.h>

#define BB 2
#define TT 2048
#define CC 768
#define HH 12
#define DD 64
#define BT (BB*TT)          // 4096 rows
#define C4 (4*CC)           // 3072
#define SCALE 0.03608439182435161f   // 1/sqrt(768)

// ---------------- scratch (static device allocations; no runtime alloc) ----
__device__ float g_h  [BT*CC];
__device__ float g_q  [BT*CC];   // layout [B,T, H*D] == [BT, C]
__device__ float g_k  [BT*CC];
__device__ float g_v  [BT*CC];
__device__ float g_att[BT*CC];
__device__ float g_x1 [BT*CC];
__device__ float g_h2 [BT*CC];
__device__ float g_hid[(size_t)BT*C4];

// ---------------- LayerNorm (optionally fused residual add) ----------------
// one block (256 thr) per row of C=768; ADD: in = x + att, also writes x1.
template<bool ADD>
__global__ __launch_bounds__(256) void ln_kernel(
    const float* __restrict__ x, const float* __restrict__ add,
    const float* __restrict__ g, const float* __restrict__ be,
    float* __restrict__ outn, float* __restrict__ outsum)
{
    int row = blockIdx.x;
    int tid = threadIdx.x;
    const float* xr = x + (size_t)row*CC;
    const float* ar = add + (size_t)row*CC;
    float v[3]; float s = 0.f, sq = 0.f;
    #pragma unroll
    for (int i = 0; i < 3; i++) {
        int c = tid + i*256;
        float val = xr[c];
        if (ADD) val += ar[c];
        v[i] = val; s += val; sq = fmaf(val, val, sq);
    }
    #pragma unroll
    for (int o = 16; o > 0; o >>= 1) {
        s  += __shfl_down_sync(0xffffffffu, s,  o);
        sq += __shfl_down_sync(0xffffffffu, sq, o);
    }
    __shared__ float rs[8], rq[8], stat[2];
    if ((tid & 31) == 0) { rs[tid>>5] = s; rq[tid>>5] = sq; }
    __syncthreads();
    if (tid == 0) {
        float ts = 0.f, tq = 0.f;
        #pragma unroll
        for (int i = 0; i < 8; i++) { ts += rs[i]; tq += rq[i]; }
        float mu  = ts * (1.0f/CC);
        float var = tq * (1.0f/CC) - mu*mu;
        stat[0] = mu; stat[1] = rsqrtf(var + 1e-5f);
    }
    __syncthreads();
    float mu = stat[0], rstd = stat[1];
    #pragma unroll
    for (int i = 0; i < 3; i++) {
        int c = tid + i*256;
        outn[(size_t)row*CC + c] = (v[i]-mu)*rstd*g[c] + be[c];
        if (ADD) outsum[(size_t)row*CC + c] = v[i];
    }
}

// ---------------- SGEMM: C[M,N] = A[M,K] * B[K,N] (+epilogue) --------------
// tile 128x64x16, 128 threads, 8x8 microtile.
// MODE 0: plain store   MODE 1: +bias, ReLU   MODE 2: +bias, +residual
template<int MODE>
__global__ __launch_bounds__(128) void sgemm_kernel(
    const float* __restrict__ A, int lda, int strideA,
    const float* __restrict__ Bm, int ldb, int strideB,
    float* __restrict__ Cm, int ldc, int strideC,
    int K,
    const float* __restrict__ bias,
    const float* __restrict__ res)
{
    __shared__ float As[16][132];   // [k][m], padded to dodge store conflicts
    __shared__ float Bs[16][72];    // [k][n], padded
    int z = blockIdx.z;
    A  += (size_t)z * strideA;
    Bm += (size_t)z * strideB;
    Cm += (size_t)z * strideC;
    int bm = blockIdx.y * 128, bn = blockIdx.x * 64;
    int tid = threadIdx.x;
    int tx = tid & 7, ty = tid >> 3;

    float acc[8][8];
    #pragma unroll
    for (int i = 0; i < 8; i++)
        #pragma unroll
        for (int j = 0; j < 8; j++) acc[i][j] = 0.f;

    int arow = tid >> 2, ak4 = (tid & 3) * 4;

    for (int k0 = 0; k0 < K; k0 += 16) {
        #pragma unroll
        for (int i = 0; i < 4; i++) {
            int r = arow + i*32;
            float4 va = *(const float4*)(A + (size_t)(bm + r)*lda + k0 + ak4);
            As[ak4+0][r] = va.x; As[ak4+1][r] = va.y;
            As[ak4+2][r] = va.z; As[ak4+3][r] = va.w;
        }
        #pragma unroll
        for (int i = 0; i < 2; i++) {
            int idx = tid + i*128;
            int r = idx >> 4, c4 = (idx & 15) * 4;
            *(float4*)&Bs[r][c4] =
                *(const float4*)(Bm + (size_t)(k0 + r)*ldb + bn + c4);
        }
        __syncthreads();
        #pragma unroll
        for (int k = 0; k < 16; k++) {
            float ar_[8], br_[8];
            *(float4*)(ar_)   = *(const float4*)&As[k][ty*8];
            *(float4*)(ar_+4) = *(const float4*)&As[k][ty*8+4];
            *(float4*)(br_)   = *(const float4*)&Bs[k][tx*8];
            *(float4*)(br_+4) = *(const float4*)&Bs[k][tx*8+4];
            #pragma unroll
            for (int i = 0; i < 8; i++)
                #pragma unroll
                for (int j = 0; j < 8; j++)
                    acc[i][j] = fmaf(ar_[i], br_[j], acc[i][j]);
        }
        __syncthreads();
    }

    #pragma unroll
    for (int i = 0; i < 8; i++) {
        int row = bm + ty*8 + i;
        #pragma unroll
        for (int j0 = 0; j0 < 8; j0 += 4) {
            int col = bn + tx*8 + j0;
            float4 o;
            o.x = acc[i][j0];   o.y = acc[i][j0+1];
            o.z = acc[i][j0+2]; o.w = acc[i][j0+3];
            if (MODE >= 1) {
                o.x += bias[col];   o.y += bias[col+1];
                o.z += bias[col+2]; o.w += bias[col+3];
            }
            if (MODE == 1) {
                o.x = fmaxf(o.x, 0.f); o.y = fmaxf(o.y, 0.f);
                o.z = fmaxf(o.z, 0.f); o.w = fmaxf(o.w, 0.f);
            }
            if (MODE == 2) {
                float4 r4 = *(const float4*)(res + (size_t)row*ldc + col);
                o.x += r4.x; o.y += r4.y; o.z += r4.z; o.w += r4.w;
            }
            *(float4*)(Cm + (size_t)row*ldc + col) = o;
        }
    }
}

// ---------------- Flash attention (causal), fp32 ---------------------------
// grid: (T/64, B*H); 256 threads; 64x64 tiles, D=64.
#define SQ 68       // padded row stride for Qs/Kt/Vs (float4-aligned)
#define SSTR 65     // padded row stride for P (conflict-free scalar reads)

__global__ __launch_bounds__(256,2) void attn_kernel(
    const float* __restrict__ Q, const float* __restrict__ Kg,
    const float* __restrict__ Vg, float* __restrict__ O)
{
    extern __shared__ float sm[];
    float* Qs     = sm;                 // [64][SQ]   (m,d)
    float* Kt     = Qs  + 64*SQ;        // [64][SQ]   (d,n)  transposed
    float* Vs     = Kt  + 64*SQ;        // [64][SQ]   (n,d)
    float* Ss     = Vs  + 64*SQ;        // [64][SSTR] P (exp'd scores)
    float* Pmax   = Ss  + 64*SSTR;      // [64*16]
    float* Psum   = Pmax + 64*16;       // [64*16]
    float* rowM   = Psum + 64*16;       // [64]
    float* rowL   = rowM + 64;          // [64]
    float* alphaA = rowL + 64;          // [64]
    float* rowNew = alphaA + 64;        // [64]

    int qt = blockIdx.x;
    int b  = blockIdx.y / HH, h = blockIdx.y % HH;
    int tid = threadIdx.x;
    size_t base = ((size_t)b*TT)*CC + (size_t)h*DD;

    #pragma unroll
    for (int i = 0; i < 4; i++) {
        int idx = tid + i*256;
        int r = idx >> 4, c4 = (idx & 15) * 4;
        *(float4*)&Qs[r*SQ + c4] =
            *(const float4*)(Q + base + (size_t)(qt*64 + r)*CC + c4);
    }
    if (tid < 64) { rowM[tid] = -1e30f; rowL[tid] = 0.f; }

    float o[16];
    #pragma unroll
    for (int t = 0; t < 16; t++) o[t] = 0.f;
    int tm = tid >> 4, tn = tid & 15;         // S-phase: 4 rows x 4 cols each
    int mo = tid & 63, dg = (tid >> 6) * 16;  // O-phase: 1 row x 16 d each
    __syncthreads();

    for (int kt = 0; kt <= qt; kt++) {
        // load K (transposed) + V tiles
        #pragma unroll
        for (int i = 0; i < 4; i++) {
            int idx = tid + i*256;
            int r = idx >> 4, c4 = (idx & 15) * 4;
            size_t ga = base + (size_t)(kt*64 + r)*CC + c4;
            float4 kv = *(const float4*)(Kg + ga);
            Kt[(c4+0)*SQ + r] = kv.x; Kt[(c4+1)*SQ + r] = kv.y;
            Kt[(c4+2)*SQ + r] = kv.z; Kt[(c4+3)*SQ + r] = kv.w;
            *(float4*)&Vs[r*SQ + c4] = *(const float4*)(Vg + ga);
        }
        __syncthreads();

        // ---- S = Q K^T  (4x4 per thread) ----
        float s[4][4];
        #pragma unroll
        for (int i = 0; i < 4; i++)
            #pragma unroll
            for (int j = 0; j < 4; j++) s[i][j] = 0.f;
        #pragma unroll
        for (int d4 = 0; d4 < 16; d4++) {
            float qa[4][4];
            #pragma unroll
            for (int i = 0; i < 4; i++)
                *(float4*)qa[i] = *(const float4*)&Qs[(tm*4 + i)*SQ + d4*4];
            #pragma unroll
            for (int dd = 0; dd < 4; dd++) {
                float4 kk = *(const float4*)&Kt[(d4*4 + dd)*SQ + tn*4];
                #pragma unroll
                for (int i = 0; i < 4; i++) {
                    float qv = qa[i][dd];
                    s[i][0] = fmaf(qv, kk.x, s[i][0]);
                    s[i][1] = fmaf(qv, kk.y, s[i][1]);
                    s[i][2] = fmaf(qv, kk.z, s[i][2]);
                    s[i][3] = fmaf(qv, kk.w, s[i][3]);
                }
            }
        }
        // ---- scale + causal mask + partial row max ----
        #pragma unroll
        for (int i = 0; i < 4; i++) {
            int mg = qt*64 + tm*4 + i;
            float pm = -1e30f;
            #pragma unroll
            for (int j = 0; j < 4; j++) {
                int ng = kt*64 + tn*4 + j;
                float val = s[i][j] * SCALE;
                if (ng > mg) val = -1e30f;
                s[i][j] = val;
                pm = fmaxf(pm, val);
            }
            Pmax[(tm*4 + i)*16 + tn] = pm;
        }
        __syncthreads();
        // ---- row stats: new max, rescale factor ----
        if (tid < 64) {
            float m0 = rowM[tid], mm = m0;
            const float* pr = Pmax + tid*16;
            #pragma unroll
            for (int j = 0; j < 16; j++) mm = fmaxf(mm, pr[j]);
            rowNew[tid] = mm;
            alphaA[tid] = __expf(m0 - mm);
            rowM[tid]   = mm;
        }
        __syncthreads();
        // ---- P = exp(S - max), partial sums ----
        #pragma unroll
        for (int i = 0; i < 4; i++) {
            int m = tm*4 + i;
            float nm = rowNew[m];
            float ps = 0.f;
            #pragma unroll
            for (int j = 0; j < 4; j++) {
                float p = __expf(s[i][j] - nm);
                Ss[m*SSTR + tn*4 + j] = p;
                ps += p;
            }
            Psum[m*16 + tn] = ps;
        }
        __syncthreads();
        // ---- l update (64 threads) + O = alpha*O + P V (all threads) ----
        if (tid < 64) {
            float l = rowL[tid] * alphaA[tid];
            const float* pr = Psum + tid*16;
            #pragma unroll
            for (int j = 0; j < 16; j++) l += pr[j];
            rowL[tid] = l;
        }
        float a = alphaA[mo];
        #pragma unroll
        for (int t = 0; t < 16; t++) o[t] *= a;
        #pragma unroll 8
        for (int n = 0; n < 64; n++) {
            float p = Ss[mo*SSTR + n];
            #pragma unroll
            for (int j = 0; j < 16; j += 4) {
                float4 v = *(const float4*)&Vs[n*SQ + dg + j];
                o[j]   = fmaf(p, v.x, o[j]);
                o[j+1] = fmaf(p, v.y, o[j+1]);
                o[j+2] = fmaf(p, v.z, o[j+2]);
                o[j+3] = fmaf(p, v.w, o[j+3]);
            }
        }
        __syncthreads();
    }
    // ---- epilogue: O / l, write [B,T,H*D] ----
    float inv = 1.0f / rowL[mo];
    size_t go = base + (size_t)(qt*64 + mo)*CC + dg;
    #pragma unroll
    for (int j = 0; j < 16; j += 4) {
        float4 v;
        v.x = o[j]*inv; v.y = o[j+1]*inv; v.z = o[j+2]*inv; v.w = o[j+3]*inv;
        *(float4*)(O + go + j) = v;
    }
}

#define ATTN_SMEM ((3*64*SQ + 64*SSTR + 2*64*16 + 4*64) * (int)sizeof(float))

// ---------------- launch ----------------------------------------------------
extern "C" void kernel_launch(void* const* d_in, const int* in_sizes, int n_in,
                              void* d_out, int out_size)
{
    const float* x    = (const float*)d_in[0];
    const float* ln1g = (const float*)d_in[1];
    const float* ln1b = (const float*)d_in[2];
    const float* wq   = (const float*)d_in[3];
    const float* wk   = (const float*)d_in[4];
    const float* wv   = (const float*)d_in[5];
    const float* ln2g = (const float*)d_in[6];
    const float* ln2b = (const float*)d_in[7];
    const float* wh   = (const float*)d_in[8];
    const float* bh   = (const float*)d_in[9];
    const float* wp   = (const float*)d_in[10];
    const float* bp   = (const float*)d_in[11];
    float* out = (float*)d_out;

    float *h, *q, *k, *v, *att, *x1, *h2, *hid;
    cudaGetSymbolAddress((void**)&h,   g_h);
    cudaGetSymbolAddress((void**)&q,   g_q);
    cudaGetSymbolAddress((void**)&k,   g_k);
    cudaGetSymbolAddress((void**)&v,   g_v);
    cudaGetSymbolAddress((void**)&att, g_att);
    cudaGetSymbolAddress((void**)&x1,  g_x1);
    cudaGetSymbolAddress((void**)&h2,  g_h2);
    cudaGetSymbolAddress((void**)&hid, g_hid);

    // LN1
    ln_kernel<false><<<BT, 256>>>(x, x, ln1g, ln1b, h, nullptr);

    // QKV projections: batched over 12 heads, N=64 per head, out stride h*64
    dim3 gqkv(1, BT/128, HH);
    sgemm_kernel<0><<<gqkv, 128>>>(h, CC, 0, wq, DD, CC*DD, q, CC, DD, CC, nullptr, nullptr);
    sgemm_kernel<0><<<gqkv, 128>>>(h, CC, 0, wk, DD, CC*DD, k, CC, DD, CC, nullptr, nullptr);
    sgemm_kernel<0><<<gqkv, 128>>>(h, CC, 0, wv, DD, CC*DD, v, CC, DD, CC, nullptr, nullptr);

    // attention
    cudaFuncSetAttribute(attn_kernel,
                         cudaFuncAttributeMaxDynamicSharedMemorySize, ATTN_SMEM);
    attn_kernel<<<dim3(TT/64, BB*HH), 256, ATTN_SMEM>>>(q, k, v, att);

    // residual + LN2 (writes x1 and h2)
    ln_kernel<true><<<BT, 256>>>(x, att, ln2g, ln2b, h2, x1);

    // MLP
    sgemm_kernel<1><<<dim3(C4/64, BT/128, 1), 128>>>(h2, CC, 0, wh, C4, 0,
                                                     hid, C4, 0, CC, bh, nullptr);
    sgemm_kernel<2><<<dim3(CC/64, BT/128, 1), 128>>>(hid, C4, 0, wp, CC, 0,
                                                     out, CC, 0, C4, bp, x1);
}

// round 3
// speedup vs baseline: 1.8015x; 1.8015x over previous
#include <cuda_runtime.h>
#include <cuda_bf16.h>
#include <cstdint>

#define BB 2
#define TT 2048
#define CC 768
#define HH 12
#define DD 64
#define BT (BB*TT)          // 4096 rows
#define C4 (4*CC)           // 3072
#define SCALE 0.03608439182435161f   // 1/sqrt(768)

// ===================== PTX helpers (sm_80-compatible only) ==================
__device__ __forceinline__ uint32_t smem_u32(const void* p) {
    uint32_t a;
    asm("{ .reg .u64 t; cvta.to.shared.u64 t, %1; cvt.u32.u64 %0, t; }"
        : "=r"(a) : "l"(p));
    return a;
}

#define CP16(s, g) \
    asm volatile("cp.async.cg.shared.global [%0], [%1], 16;" :: "r"(s), "l"(g))
#define CP_COMMIT() asm volatile("cp.async.commit_group;" ::: "memory")
#define CP_WAIT(n)  asm volatile("cp.async.wait_group %0;" :: "n"(n) : "memory")

#define LDSM_X4(r0, r1, r2, r3, a) \
    asm volatile("ldmatrix.sync.aligned.m8n8.x4.shared.b16 {%0,%1,%2,%3}, [%4];" \
        : "=r"(r0), "=r"(r1), "=r"(r2), "=r"(r3) : "r"(a))

#define MMA_BF16(d, a, b0, b1) \
    asm volatile("mma.sync.aligned.m16n8k16.row.col.f32.bf16.bf16.f32 " \
        "{%0,%1,%2,%3}, {%4,%5,%6,%7}, {%8,%9}, {%0,%1,%2,%3};" \
        : "+f"((d)[0]), "+f"((d)[1]), "+f"((d)[2]), "+f"((d)[3]) \
        : "r"((a)[0]), "r"((a)[1]), "r"((a)[2]), "r"((a)[3]), "r"(b0), "r"(b1))

#define SWZ(x) ((x) ^ (((x) >> 3) & 0x70))

// ===================== scratch (static device memory) ======================
__device__ float g_q  [BT*CC];
__device__ float g_k  [BT*CC];
__device__ float g_v  [BT*CC];
__device__ float g_att[BT*CC];
__device__ float g_x1 [BT*CC];
__device__ __nv_bfloat16 g_hh [BT*CC],  g_hl [BT*CC];
__device__ __nv_bfloat16 g_h2h[BT*CC],  g_h2l[BT*CC];
__device__ __nv_bfloat16 g_hidh[(size_t)BT*C4], g_hidl[(size_t)BT*C4];
__device__ __nv_bfloat16 g_wqh[HH*DD*CC], g_wql[HH*DD*CC];
__device__ __nv_bfloat16 g_wkh[HH*DD*CC], g_wkl[HH*DD*CC];
__device__ __nv_bfloat16 g_wvh[HH*DD*CC], g_wvl[HH*DD*CC];
__device__ __nv_bfloat16 g_whh[(size_t)C4*CC], g_whl[(size_t)C4*CC];
__device__ __nv_bfloat16 g_wph[(size_t)CC*C4], g_wpl[(size_t)CC*C4];

__device__ __forceinline__ void split2(float v, __nv_bfloat16& hi, __nv_bfloat16& lo) {
    hi = __float2bfloat16(v);
    lo = __float2bfloat16(v - __bfloat162float(hi));
}

// ===================== transpose + bf16 split for weights ==================
// in fp32 [R, Cn] row-major -> out hi/lo bf16 [Cn, R] (K-contiguous for MMA B)
__global__ __launch_bounds__(256) void tsplit_kernel(
    const float* __restrict__ in, __nv_bfloat16* __restrict__ oh,
    __nv_bfloat16* __restrict__ ol, int R, int Cn, long strideZ)
{
    __shared__ float ts[32][33];
    size_t zo = (size_t)blockIdx.z * strideZ;
    int r0 = blockIdx.y * 32, c0 = blockIdx.x * 32;
    int tx = threadIdx.x & 31, ty = threadIdx.x >> 5;
    #pragma unroll
    for (int i = 0; i < 4; i++) {
        int r = r0 + ty + i*8;
        ts[ty + i*8][tx] = in[zo + (size_t)r*Cn + c0 + tx];
    }
    __syncthreads();
    #pragma unroll
    for (int i = 0; i < 4; i++) {
        int cc = ty + i*8;
        float v = ts[tx][cc];
        __nv_bfloat16 h, l; split2(v, h, l);
        size_t oi = zo + (size_t)(c0 + cc)*R + r0 + tx;
        oh[oi] = h; ol[oi] = l;
    }
}

// ===================== LayerNorm -> split bf16 (+opt residual) =============
template<bool ADD>
__global__ __launch_bounds__(256) void ln_kernel(
    const float* __restrict__ x, const float* __restrict__ add,
    const float* __restrict__ g, const float* __restrict__ be,
    __nv_bfloat16* __restrict__ oh, __nv_bfloat16* __restrict__ ol,
    float* __restrict__ outsum)
{
    int row = blockIdx.x;
    int tid = threadIdx.x;
    const float* xr = x + (size_t)row*CC;
    const float* ar = add + (size_t)row*CC;
    float v[3]; float s = 0.f, sq = 0.f;
    #pragma unroll
    for (int i = 0; i < 3; i++) {
        int c = tid + i*256;
        float val = xr[c];
        if (ADD) val += ar[c];
        v[i] = val; s += val; sq = fmaf(val, val, sq);
    }
    #pragma unroll
    for (int o = 16; o > 0; o >>= 1) {
        s  += __shfl_down_sync(0xffffffffu, s,  o);
        sq += __shfl_down_sync(0xffffffffu, sq, o);
    }
    __shared__ float rs[8], rq[8], stat[2];
    if ((tid & 31) == 0) { rs[tid>>5] = s; rq[tid>>5] = sq; }
    __syncthreads();
    if (tid == 0) {
        float ts = 0.f, tq = 0.f;
        #pragma unroll
        for (int i = 0; i < 8; i++) { ts += rs[i]; tq += rq[i]; }
        float mu  = ts * (1.0f/CC);
        float var = tq * (1.0f/CC) - mu*mu;
        stat[0] = mu; stat[1] = rsqrtf(var + 1e-5f);
    }
    __syncthreads();
    float mu = stat[0], rstd = stat[1];
    #pragma unroll
    for (int i = 0; i < 3; i++) {
        int c = tid + i*256;
        float val = (v[i]-mu)*rstd*g[c] + be[c];
        __nv_bfloat16 h, l; split2(val, h, l);
        oh[(size_t)row*CC + c] = h;
        ol[(size_t)row*CC + c] = l;
        if (ADD) outsum[(size_t)row*CC + c] = v[i];
    }
}

// ===================== HMMA (mma.sync) GEMM =================================
// C[M,N] = A[M,K] * B[N,K]^T with bf16 hi/lo split (3 MMA terms).
// CTA tile 128 x NT, K-step 64, cp.async 2-stage pipeline, 256 threads (8 warps).
// Warp tile 32 x NT/2. SW128 swizzled smem, ldmatrix fragments.
// MODE 0: f32 store.  MODE 1: +bias, ReLU, store split bf16 (Oh/Ol).
// MODE 2: +bias +residual, f32 store.
template<int NT, int MODE>
__global__ __launch_bounds__(256)
void mm_kernel(
    const __nv_bfloat16* __restrict__ Ah, const __nv_bfloat16* __restrict__ Al,
    int lda, long strideA,
    const __nv_bfloat16* __restrict__ Bh, const __nv_bfloat16* __restrict__ Bl,
    long strideB,
    float* __restrict__ C, int ldc, long strideC,
    int Ktot,
    const float* __restrict__ bias, const float* __restrict__ res,
    __nv_bfloat16* __restrict__ Oh, __nv_bfloat16* __restrict__ Ol, int ldo)
{
    static_assert(NT == 64 || NT == 128, "NT");
    constexpr int SA_H = 0;
    constexpr int SA_L = 16384;
    constexpr int SB_H = 32768;
    constexpr int SB_L = 32768 + NT*128;
    constexpr int STAGE = 32768 + 2*NT*128;
    constexpr int NB = NT/32;        // B g2s iters per split
    constexpr int NW = NT/2;         // warp N extent
    constexpr int NT8 = NW/8;        // 8-wide n tiles per warp
    constexpr int NT16 = NW/16;      // ldmatrix.x4 B loads per split per ktile

    extern __shared__ char smraw[];
    char* sm = (char*)(((uintptr_t)smraw + 1023) & ~(uintptr_t)1023);
    uint32_t sm32 = smem_u32(sm);

    int tid = threadIdx.x;
    int wid = tid >> 5, lane = tid & 31;
    int z = blockIdx.z;
    Ah += (size_t)z * strideA;  Al += (size_t)z * strideA;
    Bh += (size_t)z * strideB;  Bl += (size_t)z * strideB;
    if (MODE != 1) C += (size_t)z * strideC;
    int bm = blockIdx.y * 128, bn = blockIdx.x * NT;

    int wm = (wid & 3) * 32;         // warp row offset in tile
    int wn = (wid >> 2) * NW;        // warp col offset in tile

    // ldmatrix per-lane row/col selectors
    int lr = lane & 7;
    int a_r = lr + ((lane & 8) ? 8 : 0);       // A: row within 16
    int a_k = (lane & 16) ? 16 : 0;            // A: +8 k (bytes)
    int b_r = lr + ((lane & 16) ? 8 : 0);      // B: row within 16
    int b_k = (lane & 8) ? 16 : 0;             // B: +8 k (bytes)

    // g2s thread mapping: 1024 16B-chunks for A-split (4 iters), NT*8 for B-split
    int g_row = tid >> 3, g_ch = tid & 7;

    float acc[2][NT8][4];
    #pragma unroll
    for (int mt = 0; mt < 2; mt++)
        #pragma unroll
        for (int nt = 0; nt < NT8; nt++)
            #pragma unroll
            for (int j = 0; j < 4; j++) acc[mt][nt][j] = 0.f;

    int nk = Ktot >> 6;

    // ---- stage loader (cp.async) ----
    auto load_stage = [&](int t) {
        int stg = (t & 1) * STAGE;
        int k0 = t << 6;
        #pragma unroll
        for (int i = 0; i < 4; i++) {
            int row = g_row + i*32;
            uint32_t so = sm32 + stg + SWZ(row*128 + g_ch*16);
            CP16(so + SA_H, Ah + (size_t)(bm+row)*lda + k0 + g_ch*8);
            CP16(so + SA_L, Al + (size_t)(bm+row)*lda + k0 + g_ch*8);
        }
        #pragma unroll
        for (int i = 0; i < NB; i++) {
            int row = g_row + i*32;
            uint32_t so = sm32 + stg + SWZ(row*128 + g_ch*16);
            CP16(so + SB_H, Bh + (size_t)(bn+row)*lda + k0 + g_ch*8);
            CP16(so + SB_L, Bl + (size_t)(bn+row)*lda + k0 + g_ch*8);
        }
        CP_COMMIT();
    };

    load_stage(0);
    if (nk > 1) load_stage(1);

    for (int t = 0; t < nk; t++) {
        if (t < nk - 1) { CP_WAIT(1); } else { CP_WAIT(0); }
        __syncthreads();
        int stg = (t & 1) * STAGE;
        uint32_t baseA_h = sm32 + stg + SA_H;
        uint32_t baseA_l = sm32 + stg + SA_L;
        uint32_t baseB_h = sm32 + stg + SB_H;
        uint32_t baseB_l = sm32 + stg + SB_L;

        #pragma unroll
        for (int kt = 0; kt < 4; kt++) {
            int kb = kt*32;
            uint32_t ah[2][4], al[2][4];
            #pragma unroll
            for (int mt = 0; mt < 2; mt++) {
                uint32_t off = SWZ((wm + mt*16 + a_r)*128 + kb + a_k);
                LDSM_X4(ah[mt][0], ah[mt][1], ah[mt][2], ah[mt][3], baseA_h + off);
                LDSM_X4(al[mt][0], al[mt][1], al[mt][2], al[mt][3], baseA_l + off);
            }
            uint32_t bh[NT16][4], bl[NT16][4];
            #pragma unroll
            for (int n2 = 0; n2 < NT16; n2++) {
                uint32_t off = SWZ((wn + n2*16 + b_r)*128 + kb + b_k);
                LDSM_X4(bh[n2][0], bh[n2][1], bh[n2][2], bh[n2][3], baseB_h + off);
                LDSM_X4(bl[n2][0], bl[n2][1], bl[n2][2], bl[n2][3], baseB_l + off);
            }
            #pragma unroll
            for (int mt = 0; mt < 2; mt++) {
                #pragma unroll
                for (int n2 = 0; n2 < NT16; n2++) {
                    MMA_BF16(acc[mt][n2*2],   ah[mt], bh[n2][0], bh[n2][1]);
                    MMA_BF16(acc[mt][n2*2+1], ah[mt], bh[n2][2], bh[n2][3]);
                    MMA_BF16(acc[mt][n2*2],   ah[mt], bl[n2][0], bl[n2][1]);
                    MMA_BF16(acc[mt][n2*2+1], ah[mt], bl[n2][2], bl[n2][3]);
                    MMA_BF16(acc[mt][n2*2],   al[mt], bh[n2][0], bh[n2][1]);
                    MMA_BF16(acc[mt][n2*2+1], al[mt], bh[n2][2], bh[n2][3]);
                }
            }
        }
        __syncthreads();
        if (t + 2 < nk) load_stage(t + 2);
    }

    // ---- epilogue ----
    int mrow0 = bm + wm + (lane >> 2);
    int ncol0 = bn + wn + (lane & 3) * 2;
    #pragma unroll
    for (int mt = 0; mt < 2; mt++) {
        #pragma unroll
        for (int half = 0; half < 2; half++) {
            int m = mrow0 + mt*16 + half*8;
            #pragma unroll
            for (int nt = 0; nt < NT8; nt++) {
                int n = ncol0 + nt*8;
                float v0 = acc[mt][nt][half*2];
                float v1 = acc[mt][nt][half*2+1];
                if (MODE == 0) {
                    float2 o; o.x = v0; o.y = v1;
                    *(float2*)(C + (size_t)m*ldc + n) = o;
                } else if (MODE == 1) {
                    v0 = fmaxf(v0 + bias[n],   0.f);
                    v1 = fmaxf(v1 + bias[n+1], 0.f);
                    __nv_bfloat16 h0, l0, h1, l1;
                    split2(v0, h0, l0); split2(v1, h1, l1);
                    __nv_bfloat162 hh2; hh2.x = h0; hh2.y = h1;
                    __nv_bfloat162 ll2; ll2.x = l0; ll2.y = l1;
                    *(__nv_bfloat162*)(Oh + (size_t)m*ldo + n) = hh2;
                    *(__nv_bfloat162*)(Ol + (size_t)m*ldo + n) = ll2;
                } else {
                    float2 rr = *(const float2*)(res + (size_t)m*ldc + n);
                    float2 o;
                    o.x = v0 + bias[n]   + rr.x;
                    o.y = v1 + bias[n+1] + rr.y;
                    *(float2*)(C + (size_t)m*ldc + n) = o;
                }
            }
        }
    }
}

// ===================== Flash attention (causal), fp32 =======================
#define SQ 68
#define SSTR 65

__global__ __launch_bounds__(256,2) void attn_kernel(
    const float* __restrict__ Q, const float* __restrict__ Kg,
    const float* __restrict__ Vg, float* __restrict__ O)
{
    extern __shared__ float smf[];
    float* Qs     = smf;
    float* Kt     = Qs  + 64*SQ;
    float* Vs     = Kt  + 64*SQ;
    float* Ss     = Vs  + 64*SQ;
    float* Pmax   = Ss  + 64*SSTR;
    float* Psum   = Pmax + 64*16;
    float* rowM   = Psum + 64*16;
    float* rowL   = rowM + 64;
    float* alphaA = rowL + 64;
    float* rowNew = alphaA + 64;

    int qt = blockIdx.x;
    int b  = blockIdx.y / HH, h = blockIdx.y % HH;
    int tid = threadIdx.x;
    size_t base = ((size_t)b*TT)*CC + (size_t)h*DD;

    #pragma unroll
    for (int i = 0; i < 4; i++) {
        int idx = tid + i*256;
        int r = idx >> 4, c4 = (idx & 15) * 4;
        *(float4*)&Qs[r*SQ + c4] =
            *(const float4*)(Q + base + (size_t)(qt*64 + r)*CC + c4);
    }
    if (tid < 64) { rowM[tid] = -1e30f; rowL[tid] = 0.f; }

    float o[16];
    #pragma unroll
    for (int t = 0; t < 16; t++) o[t] = 0.f;
    int tm = tid >> 4, tn = tid & 15;
    int mo = tid & 63, dg = (tid >> 6) * 16;
    __syncthreads();

    for (int kt = 0; kt <= qt; kt++) {
        #pragma unroll
        for (int i = 0; i < 4; i++) {
            int idx = tid + i*256;
            int r = idx >> 4, c4 = (idx & 15) * 4;
            size_t ga = base + (size_t)(kt*64 + r)*CC + c4;
            float4 kv = *(const float4*)(Kg + ga);
            Kt[(c4+0)*SQ + r] = kv.x; Kt[(c4+1)*SQ + r] = kv.y;
            Kt[(c4+2)*SQ + r] = kv.z; Kt[(c4+3)*SQ + r] = kv.w;
            *(float4*)&Vs[r*SQ + c4] = *(const float4*)(Vg + ga);
        }
        __syncthreads();

        float s[4][4];
        #pragma unroll
        for (int i = 0; i < 4; i++)
            #pragma unroll
            for (int j = 0; j < 4; j++) s[i][j] = 0.f;
        #pragma unroll
        for (int d4 = 0; d4 < 16; d4++) {
            float qa[4][4];
            #pragma unroll
            for (int i = 0; i < 4; i++)
                *(float4*)qa[i] = *(const float4*)&Qs[(tm*4 + i)*SQ + d4*4];
            #pragma unroll
            for (int dd = 0; dd < 4; dd++) {
                float4 kk = *(const float4*)&Kt[(d4*4 + dd)*SQ + tn*4];
                #pragma unroll
                for (int i = 0; i < 4; i++) {
                    float qv = qa[i][dd];
                    s[i][0] = fmaf(qv, kk.x, s[i][0]);
                    s[i][1] = fmaf(qv, kk.y, s[i][1]);
                    s[i][2] = fmaf(qv, kk.z, s[i][2]);
                    s[i][3] = fmaf(qv, kk.w, s[i][3]);
                }
            }
        }
        #pragma unroll
        for (int i = 0; i < 4; i++) {
            int mg = qt*64 + tm*4 + i;
            float pm = -1e30f;
            #pragma unroll
            for (int j = 0; j < 4; j++) {
                int ng = kt*64 + tn*4 + j;
                float val = s[i][j] * SCALE;
                if (ng > mg) val = -1e30f;
                s[i][j] = val;
                pm = fmaxf(pm, val);
            }
            Pmax[(tm*4 + i)*16 + tn] = pm;
        }
        __syncthreads();
        if (tid < 64) {
            float m0 = rowM[tid], mm = m0;
            const float* pr = Pmax + tid*16;
            #pragma unroll
            for (int j = 0; j < 16; j++) mm = fmaxf(mm, pr[j]);
            rowNew[tid] = mm;
            alphaA[tid] = __expf(m0 - mm);
            rowM[tid]   = mm;
        }
        __syncthreads();
        #pragma unroll
        for (int i = 0; i < 4; i++) {
            int m = tm*4 + i;
            float nm = rowNew[m];
            float ps = 0.f;
            #pragma unroll
            for (int j = 0; j < 4; j++) {
                float p = __expf(s[i][j] - nm);
                Ss[m*SSTR + tn*4 + j] = p;
                ps += p;
            }
            Psum[m*16 + tn] = ps;
        }
        __syncthreads();
        if (tid < 64) {
            float l = rowL[tid] * alphaA[tid];
            const float* pr = Psum + tid*16;
            #pragma unroll
            for (int j = 0; j < 16; j++) l += pr[j];
            rowL[tid] = l;
        }
        float a = alphaA[mo];
        #pragma unroll
        for (int t = 0; t < 16; t++) o[t] *= a;
        #pragma unroll 8
        for (int n = 0; n < 64; n++) {
            float p = Ss[mo*SSTR + n];
            #pragma unroll
            for (int j = 0; j < 16; j += 4) {
                float4 v = *(const float4*)&Vs[n*SQ + dg + j];
                o[j]   = fmaf(p, v.x, o[j]);
                o[j+1] = fmaf(p, v.y, o[j+1]);
                o[j+2] = fmaf(p, v.z, o[j+2]);
                o[j+3] = fmaf(p, v.w, o[j+3]);
            }
        }
        __syncthreads();
    }
    float inv = 1.0f / rowL[mo];
    size_t go = base + (size_t)(qt*64 + mo)*CC + dg;
    #pragma unroll
    for (int j = 0; j < 16; j += 4) {
        float4 v;
        v.x = o[j]*inv; v.y = o[j+1]*inv; v.z = o[j+2]*inv; v.w = o[j+3]*inv;
        *(float4*)(O + go + j) = v;
    }
}

#define ATTN_SMEM ((3*64*SQ + 64*SSTR + 2*64*16 + 4*64) * (int)sizeof(float))
#define MM_SMEM(NT) (1024 + 2*(32768 + 2*(NT)*128))

// ===================== launch ===============================================
extern "C" void kernel_launch(void* const* d_in, const int* in_sizes, int n_in,
                              void* d_out, int out_size)
{
    const float* x    = (const float*)d_in[0];
    const float* ln1g = (const float*)d_in[1];
    const float* ln1b = (const float*)d_in[2];
    const float* wq   = (const float*)d_in[3];
    const float* wk   = (const float*)d_in[4];
    const float* wv   = (const float*)d_in[5];
    const float* ln2g = (const float*)d_in[6];
    const float* ln2b = (const float*)d_in[7];
    const float* wh   = (const float*)d_in[8];
    const float* bh   = (const float*)d_in[9];
    const float* wp   = (const float*)d_in[10];
    const float* bp   = (const float*)d_in[11];
    float* out = (float*)d_out;

    float *q, *k, *v, *att, *x1;
    __nv_bfloat16 *hh, *hl, *h2h, *h2l, *hidh, *hidl;
    __nv_bfloat16 *wqh, *wql, *wkh, *wkl, *wvh, *wvl, *whh, *whl, *wph, *wpl;
    cudaGetSymbolAddress((void**)&q,    g_q);
    cudaGetSymbolAddress((void**)&k,    g_k);
    cudaGetSymbolAddress((void**)&v,    g_v);
    cudaGetSymbolAddress((void**)&att,  g_att);
    cudaGetSymbolAddress((void**)&x1,   g_x1);
    cudaGetSymbolAddress((void**)&hh,   g_hh);
    cudaGetSymbolAddress((void**)&hl,   g_hl);
    cudaGetSymbolAddress((void**)&h2h,  g_h2h);
    cudaGetSymbolAddress((void**)&h2l,  g_h2l);
    cudaGetSymbolAddress((void**)&hidh, g_hidh);
    cudaGetSymbolAddress((void**)&hidl, g_hidl);
    cudaGetSymbolAddress((void**)&wqh,  g_wqh);
    cudaGetSymbolAddress((void**)&wql,  g_wql);
    cudaGetSymbolAddress((void**)&wkh,  g_wkh);
    cudaGetSymbolAddress((void**)&wkl,  g_wkl);
    cudaGetSymbolAddress((void**)&wvh,  g_wvh);
    cudaGetSymbolAddress((void**)&wvl,  g_wvl);
    cudaGetSymbolAddress((void**)&whh,  g_whh);
    cudaGetSymbolAddress((void**)&whl,  g_whl);
    cudaGetSymbolAddress((void**)&wph,  g_wph);
    cudaGetSymbolAddress((void**)&wpl,  g_wpl);

    cudaFuncSetAttribute(attn_kernel,
        cudaFuncAttributeMaxDynamicSharedMemorySize, ATTN_SMEM);
    cudaFuncSetAttribute(mm_kernel<64,0>,
        cudaFuncAttributeMaxDynamicSharedMemorySize, MM_SMEM(64));
    cudaFuncSetAttribute(mm_kernel<128,1>,
        cudaFuncAttributeMaxDynamicSharedMemorySize, MM_SMEM(128));
    cudaFuncSetAttribute(mm_kernel<128,2>,
        cudaFuncAttributeMaxDynamicSharedMemorySize, MM_SMEM(128));

    // weight prep: transpose + bf16 split
    tsplit_kernel<<<dim3(2, 24, HH), 256>>>(wq, wqh, wql, CC, DD, (long)CC*DD);
    tsplit_kernel<<<dim3(2, 24, HH), 256>>>(wk, wkh, wkl, CC, DD, (long)CC*DD);
    tsplit_kernel<<<dim3(2, 24, HH), 256>>>(wv, wvh, wvl, CC, DD, (long)CC*DD);
    tsplit_kernel<<<dim3(96, 24, 1), 256>>>(wh, whh, whl, CC, C4, 0);
    tsplit_kernel<<<dim3(24, 96, 1), 256>>>(wp, wph, wpl, C4, CC, 0);

    // LN1 -> split bf16
    ln_kernel<false><<<BT, 256>>>(x, x, ln1g, ln1b, hh, hl, nullptr);

    // QKV projections (HMMA), batched over heads
    dim3 gq(1, BT/128, HH);
    mm_kernel<64,0><<<gq, 256, MM_SMEM(64)>>>(hh, hl, CC, 0, wqh, wql, (long)DD*CC,
        q, CC, DD, CC, nullptr, nullptr, nullptr, nullptr, 0);
    mm_kernel<64,0><<<gq, 256, MM_SMEM(64)>>>(hh, hl, CC, 0, wkh, wkl, (long)DD*CC,
        k, CC, DD, CC, nullptr, nullptr, nullptr, nullptr, 0);
    mm_kernel<64,0><<<gq, 256, MM_SMEM(64)>>>(hh, hl, CC, 0, wvh, wvl, (long)DD*CC,
        v, CC, DD, CC, nullptr, nullptr, nullptr, nullptr, 0);

    // attention (fp32 flash)
    attn_kernel<<<dim3(TT/64, BB*HH), 256, ATTN_SMEM>>>(q, k, v, att);

    // residual + LN2 -> split bf16 (+x1)
    ln_kernel<true><<<BT, 256>>>(x, att, ln2g, ln2b, h2h, h2l, x1);

    // MLP (HMMA)
    mm_kernel<128,1><<<dim3(C4/128, BT/128, 1), 256, MM_SMEM(128)>>>(
        h2h, h2l, CC, 0, whh, whl, 0, nullptr, 0, 0, CC, bh, nullptr,
        hidh, hidl, C4);
    mm_kernel<128,2><<<dim3(CC/128, BT/128, 1), 256, MM_SMEM(128)>>>(
        hidh, hidl, C4, 0, wph, wpl, 0, out, CC, 0, C4, bp, x1,
        nullptr, nullptr, 0);
}

// round 4
// speedup vs baseline: 3.1638x; 1.7561x over previous
#include <cuda_runtime.h>
#include <cuda_bf16.h>
#include <cstdint>

#define BB 2
#define TT 2048
#define CC 768
#define HH 12
#define DD 64
#define BT (BB*TT)          // 4096 rows
#define C4 (4*CC)           // 3072
#define SCALE 0.03608439182435161f   // 1/sqrt(768)

// ===================== PTX helpers (sm_80-compatible only) ==================
__device__ __forceinline__ uint32_t smem_u32(const void* p) {
    uint32_t a;
    asm("{ .reg .u64 t; cvta.to.shared.u64 t, %1; cvt.u32.u64 %0, t; }"
        : "=r"(a) : "l"(p));
    return a;
}

#define CP16(s, g) \
    asm volatile("cp.async.cg.shared.global [%0], [%1], 16;" :: "r"(s), "l"(g))
#define CP_COMMIT() asm volatile("cp.async.commit_group;" ::: "memory")
#define CP_WAIT(n)  asm volatile("cp.async.wait_group %0;" :: "n"(n) : "memory")

#define LDSM_X4(r0, r1, r2, r3, a) \
    asm volatile("ldmatrix.sync.aligned.m8n8.x4.shared.b16 {%0,%1,%2,%3}, [%4];" \
        : "=r"(r0), "=r"(r1), "=r"(r2), "=r"(r3) : "r"(a))

#define LDSM_X4T(r0, r1, r2, r3, a) \
    asm volatile("ldmatrix.sync.aligned.m8n8.x4.trans.shared.b16 {%0,%1,%2,%3}, [%4];" \
        : "=r"(r0), "=r"(r1), "=r"(r2), "=r"(r3) : "r"(a))

#define MMA_BF16(d, a, b0, b1) \
    asm volatile("mma.sync.aligned.m16n8k16.row.col.f32.bf16.bf16.f32 " \
        "{%0,%1,%2,%3}, {%4,%5,%6,%7}, {%8,%9}, {%0,%1,%2,%3};" \
        : "+f"((d)[0]), "+f"((d)[1]), "+f"((d)[2]), "+f"((d)[3]) \
        : "r"((a)[0]), "r"((a)[1]), "r"((a)[2]), "r"((a)[3]), "r"(b0), "r"(b1))

#define SWZ(x) ((x) ^ (((x) >> 3) & 0x70))

__device__ __forceinline__ uint32_t pack_bf2(float lo, float hi) {
    uint32_t r;
    asm("cvt.rn.bf16x2.f32 %0, %1, %2;" : "=r"(r) : "f"(hi), "f"(lo));
    return r;
}
__device__ __forceinline__ float2 unpack_bf2(uint32_t u) {
    __nv_bfloat162 t = *reinterpret_cast<__nv_bfloat162*>(&u);
    return make_float2(__bfloat162float(t.x), __bfloat162float(t.y));
}

// ===================== scratch (static device memory) ======================
__device__ float g_att[BT*CC];
__device__ float g_x1 [BT*CC];
__device__ __nv_bfloat16 g_hh [BT*CC],  g_hl [BT*CC];
__device__ __nv_bfloat16 g_h2h[BT*CC],  g_h2l[BT*CC];
__device__ __nv_bfloat16 g_hidh[(size_t)BT*C4], g_hidl[(size_t)BT*C4];
// qkv split, layout [B,H,T,D]
__device__ __nv_bfloat16 g_qh[BT*CC], g_ql[BT*CC];
__device__ __nv_bfloat16 g_kh[BT*CC], g_kl[BT*CC];
__device__ __nv_bfloat16 g_vh[BT*CC], g_vl[BT*CC];
__device__ __nv_bfloat16 g_wqh[HH*DD*CC], g_wql[HH*DD*CC];
__device__ __nv_bfloat16 g_wkh[HH*DD*CC], g_wkl[HH*DD*CC];
__device__ __nv_bfloat16 g_wvh[HH*DD*CC], g_wvl[HH*DD*CC];
__device__ __nv_bfloat16 g_whh[(size_t)C4*CC], g_whl[(size_t)C4*CC];
__device__ __nv_bfloat16 g_wph[(size_t)CC*C4], g_wpl[(size_t)CC*C4];

__device__ __forceinline__ void split2(float v, __nv_bfloat16& hi, __nv_bfloat16& lo) {
    hi = __float2bfloat16(v);
    lo = __float2bfloat16(v - __bfloat162float(hi));
}

struct QKVOut {
    const __nv_bfloat16 *wh0, *wl0, *wh1, *wl1, *wh2, *wl2;
    __nv_bfloat16 *qh, *ql, *kh, *kl, *vh, *vl;
};

// ===================== transpose + bf16 split for weights ==================
__global__ __launch_bounds__(256) void tsplit_kernel(
    const float* __restrict__ in, __nv_bfloat16* __restrict__ oh,
    __nv_bfloat16* __restrict__ ol, int R, int Cn, long strideZ)
{
    __shared__ float ts[32][33];
    size_t zo = (size_t)blockIdx.z * strideZ;
    int r0 = blockIdx.y * 32, c0 = blockIdx.x * 32;
    int tx = threadIdx.x & 31, ty = threadIdx.x >> 5;
    #pragma unroll
    for (int i = 0; i < 4; i++) {
        int r = r0 + ty + i*8;
        ts[ty + i*8][tx] = in[zo + (size_t)r*Cn + c0 + tx];
    }
    __syncthreads();
    #pragma unroll
    for (int i = 0; i < 4; i++) {
        int cc = ty + i*8;
        float v = ts[tx][cc];
        __nv_bfloat16 h, l; split2(v, h, l);
        size_t oi = zo + (size_t)(c0 + cc)*R + r0 + tx;
        oh[oi] = h; ol[oi] = l;
    }
}

// ===================== LayerNorm -> split bf16 (+opt residual) =============
template<bool ADD>
__global__ __launch_bounds__(256) void ln_kernel(
    const float* __restrict__ x, const float* __restrict__ add,
    const float* __restrict__ g, const float* __restrict__ be,
    __nv_bfloat16* __restrict__ oh, __nv_bfloat16* __restrict__ ol,
    float* __restrict__ outsum)
{
    int row = blockIdx.x;
    int tid = threadIdx.x;
    const float* xr = x + (size_t)row*CC;
    const float* ar = add + (size_t)row*CC;
    float v[3]; float s = 0.f, sq = 0.f;
    #pragma unroll
    for (int i = 0; i < 3; i++) {
        int c = tid + i*256;
        float val = xr[c];
        if (ADD) val += ar[c];
        v[i] = val; s += val; sq = fmaf(val, val, sq);
    }
    #pragma unroll
    for (int o = 16; o > 0; o >>= 1) {
        s  += __shfl_down_sync(0xffffffffu, s,  o);
        sq += __shfl_down_sync(0xffffffffu, sq, o);
    }
    __shared__ float rs[8], rq[8], stat[2];
    if ((tid & 31) == 0) { rs[tid>>5] = s; rq[tid>>5] = sq; }
    __syncthreads();
    if (tid == 0) {
        float ts = 0.f, tq = 0.f;
        #pragma unroll
        for (int i = 0; i < 8; i++) { ts += rs[i]; tq += rq[i]; }
        float mu  = ts * (1.0f/CC);
        float var = tq * (1.0f/CC) - mu*mu;
        stat[0] = mu; stat[1] = rsqrtf(var + 1e-5f);
    }
    __syncthreads();
    float mu = stat[0], rstd = stat[1];
    #pragma unroll
    for (int i = 0; i < 3; i++) {
        int c = tid + i*256;
        float val = (v[i]-mu)*rstd*g[c] + be[c];
        __nv_bfloat16 h, l; split2(val, h, l);
        oh[(size_t)row*CC + c] = h;
        ol[(size_t)row*CC + c] = l;
        if (ADD) outsum[(size_t)row*CC + c] = v[i];
    }
}

// ===================== HMMA (mma.sync) GEMM =================================
// C[M,N] = A[M,K] * B[N,K]^T with bf16 hi/lo split (3 MMA terms).
// MODE 1: +bias, ReLU, store split bf16.  MODE 2: +bias +residual, f32 store.
// MODE 3: fused QKV: z = proj*HH + h, B from qkv struct, out split bf16 to
//         [B,H,T,D], Q pre-scaled by SCALE.
template<int NT, int MODE>
__global__ __launch_bounds__(256)
void mm_kernel(
    const __nv_bfloat16* __restrict__ Ah, const __nv_bfloat16* __restrict__ Al,
    int lda, long strideA,
    const __nv_bfloat16* __restrict__ Bh, const __nv_bfloat16* __restrict__ Bl,
    long strideB,
    float* __restrict__ C, int ldc, long strideC,
    int Ktot,
    const float* __restrict__ bias, const float* __restrict__ res,
    __nv_bfloat16* __restrict__ Oh, __nv_bfloat16* __restrict__ Ol, int ldo,
    QKVOut qkv)
{
    static_assert(NT == 64 || NT == 128, "NT");
    constexpr int SA_H = 0;
    constexpr int SA_L = 16384;
    constexpr int SB_H = 32768;
    constexpr int SB_L = 32768 + NT*128;
    constexpr int STAGE = 32768 + 2*NT*128;
    constexpr int NB = NT/32;
    constexpr int NW = NT/2;
    constexpr int NT8 = NW/8;
    constexpr int NT16 = NW/16;

    extern __shared__ char smraw[];
    char* sm = (char*)(((uintptr_t)smraw + 1023) & ~(uintptr_t)1023);
    uint32_t sm32 = smem_u32(sm);

    int tid = threadIdx.x;
    int wid = tid >> 5, lane = tid & 31;
    int z = blockIdx.z;
    int proj = 0, hsel = 0;
    if (MODE == 3) {
        proj = z / HH; hsel = z % HH;
        const __nv_bfloat16* wh = (proj == 0) ? qkv.wh0 : (proj == 1) ? qkv.wh1 : qkv.wh2;
        const __nv_bfloat16* wl = (proj == 0) ? qkv.wl0 : (proj == 1) ? qkv.wl1 : qkv.wl2;
        Bh = wh + (size_t)hsel*CC*DD;
        Bl = wl + (size_t)hsel*CC*DD;
    } else {
        Ah += (size_t)z * strideA;  Al += (size_t)z * strideA;
        Bh += (size_t)z * strideB;  Bl += (size_t)z * strideB;
        if (MODE == 2) C += (size_t)z * strideC;
    }
    int bm = blockIdx.y * 128, bn = blockIdx.x * NT;

    int wm = (wid & 3) * 32;
    int wn = (wid >> 2) * NW;

    int lr = lane & 7;
    int a_r = lr + ((lane & 8) ? 8 : 0);
    int a_k = (lane & 16) ? 16 : 0;
    int b_r = lr + ((lane & 16) ? 8 : 0);
    int b_k = (lane & 8) ? 16 : 0;

    int g_row = tid >> 3, g_ch = tid & 7;

    float acc[2][NT8][4];
    #pragma unroll
    for (int mt = 0; mt < 2; mt++)
        #pragma unroll
        for (int nt = 0; nt < NT8; nt++)
            #pragma unroll
            for (int j = 0; j < 4; j++) acc[mt][nt][j] = 0.f;

    int nk = Ktot >> 6;

    auto load_stage = [&](int t) {
        int stg = (t & 1) * STAGE;
        int k0 = t << 6;
        #pragma unroll
        for (int i = 0; i < 4; i++) {
            int row = g_row + i*32;
            uint32_t so = sm32 + stg + SWZ(row*128 + g_ch*16);
            CP16(so + SA_H, Ah + (size_t)(bm+row)*lda + k0 + g_ch*8);
            CP16(so + SA_L, Al + (size_t)(bm+row)*lda + k0 + g_ch*8);
        }
        #pragma unroll
        for (int i = 0; i < NB; i++) {
            int row = g_row + i*32;
            uint32_t so = sm32 + stg + SWZ(row*128 + g_ch*16);
            CP16(so + SB_H, Bh + (size_t)(bn+row)*lda + k0 + g_ch*8);
            CP16(so + SB_L, Bl + (size_t)(bn+row)*lda + k0 + g_ch*8);
        }
        CP_COMMIT();
    };

    load_stage(0);
    if (nk > 1) load_stage(1);

    for (int t = 0; t < nk; t++) {
        if (t < nk - 1) { CP_WAIT(1); } else { CP_WAIT(0); }
        __syncthreads();
        int stg = (t & 1) * STAGE;
        uint32_t baseA_h = sm32 + stg + SA_H;
        uint32_t baseA_l = sm32 + stg + SA_L;
        uint32_t baseB_h = sm32 + stg + SB_H;
        uint32_t baseB_l = sm32 + stg + SB_L;

        #pragma unroll
        for (int kt = 0; kt < 4; kt++) {
            int kb = kt*32;
            uint32_t ah[2][4], al[2][4];
            #pragma unroll
            for (int mt = 0; mt < 2; mt++) {
                uint32_t off = SWZ((wm + mt*16 + a_r)*128 + kb + a_k);
                LDSM_X4(ah[mt][0], ah[mt][1], ah[mt][2], ah[mt][3], baseA_h + off);
                LDSM_X4(al[mt][0], al[mt][1], al[mt][2], al[mt][3], baseA_l + off);
            }
            uint32_t bh[NT16][4], bl[NT16][4];
            #pragma unroll
            for (int n2 = 0; n2 < NT16; n2++) {
                uint32_t off = SWZ((wn + n2*16 + b_r)*128 + kb + b_k);
                LDSM_X4(bh[n2][0], bh[n2][1], bh[n2][2], bh[n2][3], baseB_h + off);
                LDSM_X4(bl[n2][0], bl[n2][1], bl[n2][2], bl[n2][3], baseB_l + off);
            }
            #pragma unroll
            for (int mt = 0; mt < 2; mt++) {
                #pragma unroll
                for (int n2 = 0; n2 < NT16; n2++) {
                    MMA_BF16(acc[mt][n2*2],   ah[mt], bh[n2][0], bh[n2][1]);
                    MMA_BF16(acc[mt][n2*2+1], ah[mt], bh[n2][2], bh[n2][3]);
                    MMA_BF16(acc[mt][n2*2],   ah[mt], bl[n2][0], bl[n2][1]);
                    MMA_BF16(acc[mt][n2*2+1], ah[mt], bl[n2][2], bl[n2][3]);
                    MMA_BF16(acc[mt][n2*2],   al[mt], bh[n2][0], bh[n2][1]);
                    MMA_BF16(acc[mt][n2*2+1], al[mt], bh[n2][2], bh[n2][3]);
                }
            }
        }
        __syncthreads();
        if (t + 2 < nk) load_stage(t + 2);
    }

    // ---- epilogue ----
    int mrow0 = bm + wm + (lane >> 2);
    int ncol0 = bn + wn + (lane & 3) * 2;
    #pragma unroll
    for (int mt = 0; mt < 2; mt++) {
        #pragma unroll
        for (int half = 0; half < 2; half++) {
            int m = mrow0 + mt*16 + half*8;
            #pragma unroll
            for (int nt = 0; nt < NT8; nt++) {
                int n = ncol0 + nt*8;
                float v0 = acc[mt][nt][half*2];
                float v1 = acc[mt][nt][half*2+1];
                if (MODE == 1) {
                    v0 = fmaxf(v0 + bias[n],   0.f);
                    v1 = fmaxf(v1 + bias[n+1], 0.f);
                    __nv_bfloat16 h0, l0, h1, l1;
                    split2(v0, h0, l0); split2(v1, h1, l1);
                    __nv_bfloat162 hh2; hh2.x = h0; hh2.y = h1;
                    __nv_bfloat162 ll2; ll2.x = l0; ll2.y = l1;
                    *(__nv_bfloat162*)(Oh + (size_t)m*ldo + n) = hh2;
                    *(__nv_bfloat162*)(Ol + (size_t)m*ldo + n) = ll2;
                } else if (MODE == 2) {
                    float2 rr = *(const float2*)(res + (size_t)m*ldc + n);
                    float2 o;
                    o.x = v0 + bias[n]   + rr.x;
                    o.y = v1 + bias[n+1] + rr.y;
                    *(float2*)(C + (size_t)m*ldc + n) = o;
                } else if (MODE == 3) {
                    float sc = (proj == 0) ? SCALE : 1.0f;
                    v0 *= sc; v1 *= sc;
                    __nv_bfloat16 h0, l0, h1, l1;
                    split2(v0, h0, l0); split2(v1, h1, l1);
                    __nv_bfloat162 hh2; hh2.x = h0; hh2.y = h1;
                    __nv_bfloat162 ll2; ll2.x = l0; ll2.y = l1;
                    __nv_bfloat16* poh = (proj == 0) ? qkv.qh : (proj == 1) ? qkv.kh : qkv.vh;
                    __nv_bfloat16* pol = (proj == 0) ? qkv.ql : (proj == 1) ? qkv.kl : qkv.vl;
                    int bidx = m >> 11, tt = m & (TT-1);
                    size_t o = (((size_t)bidx*HH + hsel)*TT + tt)*DD + n;
                    *(__nv_bfloat162*)(poh + o) = hh2;
                    *(__nv_bfloat162*)(pol + o) = ll2;
                }
            }
        }
    }
}

// ===================== HMMA flash attention (causal) ========================
// grid (32, 24) reversed-qt, 128 threads (4 warps), warp owns 16 q rows.
// Q pre-scaled by 1/sqrt(C). hi/lo split, 3-term MMA for QK^T and PV.
__global__ __launch_bounds__(128) void attn_kernel(
    const __nv_bfloat16* __restrict__ Qh, const __nv_bfloat16* __restrict__ Ql,
    const __nv_bfloat16* __restrict__ Kh, const __nv_bfloat16* __restrict__ Kl,
    const __nv_bfloat16* __restrict__ Vh, const __nv_bfloat16* __restrict__ Vl,
    float* __restrict__ O)
{
    extern __shared__ char smraw[];
    char* sm = (char*)(((uintptr_t)smraw + 1023) & ~(uintptr_t)1023);
    uint32_t sm32 = smem_u32(sm);

    constexpr int QH_O = 0, QL_O = 8192, STG_O = 16384, STG_SZ = 32768;
    // in-stage: KH +0, KL +8192, VH +16384, VL +24576

    int qt = gridDim.x - 1 - (int)blockIdx.x;   // longest first
    int bh = blockIdx.y;
    int b = bh / HH, h = bh % HH;
    int tid = threadIdx.x, wid = tid >> 5, lane = tid & 31;
    size_t base = (size_t)bh * TT * DD;

    // ---- issue Q loads (part of group 0) ----
    #pragma unroll
    for (int i = 0; i < 4; i++) {
        int idx = tid + i*128; int row = idx >> 3, ch = idx & 7;
        uint32_t so = sm32 + SWZ(row*128 + ch*16);
        size_t ga = base + (size_t)(qt*64 + row)*DD + ch*8;
        CP16(so + QH_O, Qh + ga);
        CP16(so + QL_O, Ql + ga);
    }
    auto load_kv = [&](int kt) {
        int stg = STG_O + (kt & 1) * STG_SZ;
        #pragma unroll
        for (int i = 0; i < 4; i++) {
            int idx = tid + i*128; int row = idx >> 3, ch = idx & 7;
            uint32_t so = sm32 + stg + SWZ(row*128 + ch*16);
            size_t ga = base + (size_t)(kt*64 + row)*DD + ch*8;
            CP16(so,         Kh + ga);
            CP16(so + 8192,  Kl + ga);
            CP16(so + 16384, Vh + ga);
            CP16(so + 24576, Vl + ga);
        }
        CP_COMMIT();
    };
    load_kv(0);                 // group 0 (includes Q)
    if (qt >= 1) load_kv(1);    // group 1

    int lr = lane & 7;
    int a_r = lr + ((lane & 8) ? 8 : 0);
    int a_k = (lane & 16) ? 16 : 0;
    int b_r = lr + ((lane & 16) ? 8 : 0);
    int b_k = (lane & 8) ? 16 : 0;
    int v_r = lr + ((lane & 8) ? 8 : 0);    // trans (V) addressing
    int v_k = (lane & 16) ? 16 : 0;
    int wm = wid * 16;

    float o[8][4];
    #pragma unroll
    for (int nf = 0; nf < 8; nf++)
        #pragma unroll
        for (int j = 0; j < 4; j++) o[nf][j] = 0.f;
    float mrow0 = -1e30f, mrow1 = -1e30f, lrow0 = 0.f, lrow1 = 0.f;

    if (qt >= 1) { CP_WAIT(1); } else { CP_WAIT(0); }
    __syncthreads();

    // Q fragments resident in registers for the whole kernel
    uint32_t qhf[4][4], qlf[4][4];
    #pragma unroll
    for (int kc = 0; kc < 4; kc++) {
        uint32_t off = SWZ((wm + a_r)*128 + kc*32 + a_k);
        LDSM_X4(qhf[kc][0], qhf[kc][1], qhf[kc][2], qhf[kc][3], sm32 + QH_O + off);
        LDSM_X4(qlf[kc][0], qlf[kc][1], qlf[kc][2], qlf[kc][3], sm32 + QL_O + off);
    }

    for (int kt = 0; kt <= qt; kt++) {
        if (kt > 0) {
            if (kt < qt) { CP_WAIT(1); } else { CP_WAIT(0); }
            __syncthreads();
        }
        uint32_t kbh = sm32 + STG_O + (kt & 1)*STG_SZ;
        uint32_t kbl = kbh + 8192, vbh = kbh + 16384, vbl = kbh + 24576;

        // ---- S = Q K^T (3-term) ----
        float s[8][4];
        #pragma unroll
        for (int nf = 0; nf < 8; nf++)
            #pragma unroll
            for (int j = 0; j < 4; j++) s[nf][j] = 0.f;

        #pragma unroll
        for (int kc = 0; kc < 4; kc++) {
            #pragma unroll
            for (int c2 = 0; c2 < 4; c2++) {
                uint32_t h4[4], l4[4];
                uint32_t off = SWZ((c2*16 + b_r)*128 + kc*32 + b_k);
                LDSM_X4(h4[0], h4[1], h4[2], h4[3], kbh + off);
                LDSM_X4(l4[0], l4[1], l4[2], l4[3], kbl + off);
                MMA_BF16(s[c2*2],   qhf[kc], h4[0], h4[1]);
                MMA_BF16(s[c2*2+1], qhf[kc], h4[2], h4[3]);
                MMA_BF16(s[c2*2],   qhf[kc], l4[0], l4[1]);
                MMA_BF16(s[c2*2+1], qhf[kc], l4[2], l4[3]);
                MMA_BF16(s[c2*2],   qlf[kc], h4[0], h4[1]);
                MMA_BF16(s[c2*2+1], qlf[kc], h4[2], h4[3]);
            }
        }

        // ---- causal mask on diagonal tile ----
        if (kt == qt) {
            int r0 = wm + (lane >> 2), r1 = r0 + 8;
            #pragma unroll
            for (int nf = 0; nf < 8; nf++) {
                int c = nf*8 + (lane & 3)*2;
                if (c   > r0) s[nf][0] = -1e30f;
                if (c+1 > r0) s[nf][1] = -1e30f;
                if (c   > r1) s[nf][2] = -1e30f;
                if (c+1 > r1) s[nf][3] = -1e30f;
            }
        }

        // ---- online softmax (register-only, quad shfl reduction) ----
        float t0 = -1e30f, t1 = -1e30f;
        #pragma unroll
        for (int nf = 0; nf < 8; nf++) {
            t0 = fmaxf(t0, fmaxf(s[nf][0], s[nf][1]));
            t1 = fmaxf(t1, fmaxf(s[nf][2], s[nf][3]));
        }
        t0 = fmaxf(t0, __shfl_xor_sync(0xffffffffu, t0, 1));
        t0 = fmaxf(t0, __shfl_xor_sync(0xffffffffu, t0, 2));
        t1 = fmaxf(t1, __shfl_xor_sync(0xffffffffu, t1, 1));
        t1 = fmaxf(t1, __shfl_xor_sync(0xffffffffu, t1, 2));
        float mn0 = fmaxf(mrow0, t0), mn1 = fmaxf(mrow1, t1);
        float al0 = __expf(mrow0 - mn0), al1 = __expf(mrow1 - mn1);
        mrow0 = mn0; mrow1 = mn1;
        float ps0 = 0.f, ps1 = 0.f;
        #pragma unroll
        for (int nf = 0; nf < 8; nf++) {
            s[nf][0] = __expf(s[nf][0] - mn0);
            s[nf][1] = __expf(s[nf][1] - mn0);
            s[nf][2] = __expf(s[nf][2] - mn1);
            s[nf][3] = __expf(s[nf][3] - mn1);
            ps0 += s[nf][0] + s[nf][1];
            ps1 += s[nf][2] + s[nf][3];
        }
        ps0 += __shfl_xor_sync(0xffffffffu, ps0, 1);
        ps0 += __shfl_xor_sync(0xffffffffu, ps0, 2);
        ps1 += __shfl_xor_sync(0xffffffffu, ps1, 1);
        ps1 += __shfl_xor_sync(0xffffffffu, ps1, 2);
        lrow0 = lrow0*al0 + ps0;
        lrow1 = lrow1*al1 + ps1;
        #pragma unroll
        for (int nf = 0; nf < 8; nf++) {
            o[nf][0] *= al0; o[nf][1] *= al0;
            o[nf][2] *= al1; o[nf][3] *= al1;
        }

        // ---- O += P V (3-term; P D-frags -> A-frags in registers) ----
        #pragma unroll
        for (int sk = 0; sk < 4; sk++) {
            int f0 = sk*2, f1 = sk*2+1;
            uint32_t pha[4], pla[4];
            pha[0] = pack_bf2(s[f0][0], s[f0][1]);
            pha[1] = pack_bf2(s[f0][2], s[f0][3]);
            pha[2] = pack_bf2(s[f1][0], s[f1][1]);
            pha[3] = pack_bf2(s[f1][2], s[f1][3]);
            float2 u0 = unpack_bf2(pha[0]);
            float2 u1 = unpack_bf2(pha[1]);
            float2 u2 = unpack_bf2(pha[2]);
            float2 u3 = unpack_bf2(pha[3]);
            pla[0] = pack_bf2(s[f0][0]-u0.x, s[f0][1]-u0.y);
            pla[1] = pack_bf2(s[f0][2]-u1.x, s[f0][3]-u1.y);
            pla[2] = pack_bf2(s[f1][0]-u2.x, s[f1][1]-u2.y);
            pla[3] = pack_bf2(s[f1][2]-u3.x, s[f1][3]-u3.y);
            #pragma unroll
            for (int c2 = 0; c2 < 4; c2++) {
                uint32_t vh4[4], vl4[4];
                uint32_t off = SWZ((sk*16 + v_r)*128 + c2*32 + v_k);
                LDSM_X4T(vh4[0], vh4[1], vh4[2], vh4[3], vbh + off);
                LDSM_X4T(vl4[0], vl4[1], vl4[2], vl4[3], vbl + off);
                MMA_BF16(o[c2*2],   pha, vh4[0], vh4[1]);
                MMA_BF16(o[c2*2+1], pha, vh4[2], vh4[3]);
                MMA_BF16(o[c2*2],   pha, vl4[0], vl4[1]);
                MMA_BF16(o[c2*2+1], pha, vl4[2], vl4[3]);
                MMA_BF16(o[c2*2],   pla, vh4[0], vh4[1]);
                MMA_BF16(o[c2*2+1], pla, vh4[2], vh4[3]);
            }
        }

        __syncthreads();
        if (kt + 2 <= qt) load_kv(kt + 2);
    }

    // ---- epilogue: O / l, write f32 [B,T,C] ----
    float inv0 = 1.0f / lrow0, inv1 = 1.0f / lrow1;
    int r0 = qt*64 + wm + (lane >> 2), r1 = r0 + 8;
    size_t ob = (size_t)b * TT;
    #pragma unroll
    for (int nf = 0; nf < 8; nf++) {
        int d = nf*8 + (lane & 3)*2;
        float2 w0; w0.x = o[nf][0]*inv0; w0.y = o[nf][1]*inv0;
        float2 w1; w1.x = o[nf][2]*inv1; w1.y = o[nf][3]*inv1;
        *(float2*)(O + (ob + r0)*CC + h*DD + d) = w0;
        *(float2*)(O + (ob + r1)*CC + h*DD + d) = w1;
    }
}

#define ATTN_SMEM (1024 + 16384 + 2*32768)
#define MM_SMEM(NT) (1024 + 2*(32768 + 2*(NT)*128))

// ===================== launch ===============================================
extern "C" void kernel_launch(void* const* d_in, const int* in_sizes, int n_in,
                              void* d_out, int out_size)
{
    const float* x    = (const float*)d_in[0];
    const float* ln1g = (const float*)d_in[1];
    const float* ln1b = (const float*)d_in[2];
    const float* wq   = (const float*)d_in[3];
    const float* wk   = (const float*)d_in[4];
    const float* wv   = (const float*)d_in[5];
    const float* ln2g = (const float*)d_in[6];
    const float* ln2b = (const float*)d_in[7];
    const float* wh   = (const float*)d_in[8];
    const float* bh   = (const float*)d_in[9];
    const float* wp   = (const float*)d_in[10];
    const float* bp   = (const float*)d_in[11];
    float* out = (float*)d_out;

    float *att, *x1;
    __nv_bfloat16 *hh, *hl, *h2h, *h2l, *hidh, *hidl;
    __nv_bfloat16 *qh, *ql, *kh, *kl, *vh, *vl;
    __nv_bfloat16 *wqh, *wql, *wkh, *wkl, *wvh, *wvl, *whh, *whl, *wph, *wpl;
    cudaGetSymbolAddress((void**)&att,  g_att);
    cudaGetSymbolAddress((void**)&x1,   g_x1);
    cudaGetSymbolAddress((void**)&hh,   g_hh);
    cudaGetSymbolAddress((void**)&hl,   g_hl);
    cudaGetSymbolAddress((void**)&h2h,  g_h2h);
    cudaGetSymbolAddress((void**)&h2l,  g_h2l);
    cudaGetSymbolAddress((void**)&hidh, g_hidh);
    cudaGetSymbolAddress((void**)&hidl, g_hidl);
    cudaGetSymbolAddress((void**)&qh,   g_qh);
    cudaGetSymbolAddress((void**)&ql,   g_ql);
    cudaGetSymbolAddress((void**)&kh,   g_kh);
    cudaGetSymbolAddress((void**)&kl,   g_kl);
    cudaGetSymbolAddress((void**)&vh,   g_vh);
    cudaGetSymbolAddress((void**)&vl,   g_vl);
    cudaGetSymbolAddress((void**)&wqh,  g_wqh);
    cudaGetSymbolAddress((void**)&wql,  g_wql);
    cudaGetSymbolAddress((void**)&wkh,  g_wkh);
    cudaGetSymbolAddress((void**)&wkl,  g_wkl);
    cudaGetSymbolAddress((void**)&wvh,  g_wvh);
    cudaGetSymbolAddress((void**)&wvl,  g_wvl);
    cudaGetSymbolAddress((void**)&whh,  g_whh);
    cudaGetSymbolAddress((void**)&whl,  g_whl);
    cudaGetSymbolAddress((void**)&wph,  g_wph);
    cudaGetSymbolAddress((void**)&wpl,  g_wpl);

    cudaFuncSetAttribute(attn_kernel,
        cudaFuncAttributeMaxDynamicSharedMemorySize, ATTN_SMEM);
    cudaFuncSetAttribute(mm_kernel<64,3>,
        cudaFuncAttributeMaxDynamicSharedMemorySize, MM_SMEM(64));
    cudaFuncSetAttribute(mm_kernel<128,1>,
        cudaFuncAttributeMaxDynamicSharedMemorySize, MM_SMEM(128));
    cudaFuncSetAttribute(mm_kernel<128,2>,
        cudaFuncAttributeMaxDynamicSharedMemorySize, MM_SMEM(128));

    // weight prep: transpose + bf16 split
    tsplit_kernel<<<dim3(2, 24, HH), 256>>>(wq, wqh, wql, CC, DD, (long)CC*DD);
    tsplit_kernel<<<dim3(2, 24, HH), 256>>>(wk, wkh, wkl, CC, DD, (long)CC*DD);
    tsplit_kernel<<<dim3(2, 24, HH), 256>>>(wv, wvh, wvl, CC, DD, (long)CC*DD);
    tsplit_kernel<<<dim3(96, 24, 1), 256>>>(wh, whh, whl, CC, C4, 0);
    tsplit_kernel<<<dim3(24, 96, 1), 256>>>(wp, wph, wpl, C4, CC, 0);

    // LN1 -> split bf16
    ln_kernel<false><<<BT, 256>>>(x, x, ln1g, ln1b, hh, hl, nullptr);

    // fused QKV projection (z = proj*HH + h), epilogue writes split bf16 [B,H,T,D]
    QKVOut qkv;
    qkv.wh0 = wqh; qkv.wl0 = wql; qkv.wh1 = wkh; qkv.wl1 = wkl;
    qkv.wh2 = wvh; qkv.wl2 = wvl;
    qkv.qh = qh; qkv.ql = ql; qkv.kh = kh; qkv.kl = kl; qkv.vh = vh; qkv.vl = vl;
    QKVOut qkv0 = {};
    mm_kernel<64,3><<<dim3(1, BT/128, 3*HH), 256, MM_SMEM(64)>>>(
        hh, hl, CC, 0, nullptr, nullptr, 0,
        nullptr, 0, 0, CC, nullptr, nullptr, nullptr, nullptr, 0, qkv);

    // HMMA flash attention
    attn_kernel<<<dim3(TT/64, BB*HH), 128, ATTN_SMEM>>>(qh, ql, kh, kl, vh, vl, att);

    // residual + LN2 -> split bf16 (+x1)
    ln_kernel<true><<<BT, 256>>>(x, att, ln2g, ln2b, h2h, h2l, x1);

    // MLP (HMMA)
    mm_kernel<128,1><<<dim3(C4/128, BT/128, 1), 256, MM_SMEM(128)>>>(
        h2h, h2l, CC, 0, whh, whl, 0, nullptr, 0, 0, CC, bh, nullptr,
        hidh, hidl, C4, qkv0);
    mm_kernel<128,2><<<dim3(CC/128, BT/128, 1), 256, MM_SMEM(128)>>>(
        hidh, hidl, C4, 0, wph, wpl, 0, out, CC, 0, C4, bp, x1,
        nullptr, nullptr, 0, qkv0);
}

// round 5
// speedup vs baseline: 4.5269x; 1.4308x over previous
#include <cuda_runtime.h>
#include <cuda_fp16.h>
#include <cstdint>

#define BB 2
#define TT 2048
#define CC 768
#define HH 12
#define DD 64
#define BT (BB*TT)          // 4096 rows
#define C4 (4*CC)           // 3072
#define SCALE 0.03608439182435161f   // 1/sqrt(768)

// ===================== PTX helpers (sm_80-compatible only) ==================
__device__ __forceinline__ uint32_t smem_u32(const void* p) {
    uint32_t a;
    asm("{ .reg .u64 t; cvta.to.shared.u64 t, %1; cvt.u32.u64 %0, t; }"
        : "=r"(a) : "l"(p));
    return a;
}

#define CP16(s, g) \
    asm volatile("cp.async.cg.shared.global [%0], [%1], 16;" :: "r"(s), "l"(g))
#define CP_COMMIT() asm volatile("cp.async.commit_group;" ::: "memory")
#define CP_WAIT(n)  asm volatile("cp.async.wait_group %0;" :: "n"(n) : "memory")

#define LDSM_X4(r0, r1, r2, r3, a) \
    asm volatile("ldmatrix.sync.aligned.m8n8.x4.shared.b16 {%0,%1,%2,%3}, [%4];" \
        : "=r"(r0), "=r"(r1), "=r"(r2), "=r"(r3) : "r"(a))

#define LDSM_X4T(r0, r1, r2, r3, a) \
    asm volatile("ldmatrix.sync.aligned.m8n8.x4.trans.shared.b16 {%0,%1,%2,%3}, [%4];" \
        : "=r"(r0), "=r"(r1), "=r"(r2), "=r"(r3) : "r"(a))

#define MMA_F16(d, a, b0, b1) \
    asm volatile("mma.sync.aligned.m16n8k16.row.col.f32.f16.f16.f32 " \
        "{%0,%1,%2,%3}, {%4,%5,%6,%7}, {%8,%9}, {%0,%1,%2,%3};" \
        : "+f"((d)[0]), "+f"((d)[1]), "+f"((d)[2]), "+f"((d)[3]) \
        : "r"((a)[0]), "r"((a)[1]), "r"((a)[2]), "r"((a)[3]), "r"(b0), "r"(b1))

#define SWZ(x) ((x) ^ (((x) >> 3) & 0x70))

__device__ __forceinline__ uint32_t pack_h2(float lo, float hi) {
    uint32_t r;
    asm("cvt.rn.f16x2.f32 %0, %1, %2;" : "=r"(r) : "f"(hi), "f"(lo));
    return r;
}
__device__ __forceinline__ float2 unpack_h2(uint32_t u) {
    __half2 t = *reinterpret_cast<__half2*>(&u);
    return make_float2(__half2float(t.x), __half2float(t.y));
}

// ===================== scratch (static device memory) ======================
__device__ float g_att[BT*CC];
__device__ float g_x1 [BT*CC];
__device__ __half g_hh [BT*CC],  g_hl [BT*CC];
__device__ __half g_h2h[BT*CC],  g_h2l[BT*CC];
__device__ __half g_hidh[(size_t)BT*C4], g_hidl[(size_t)BT*C4];
// qkv, layout [B,H,T,D]; Q split hi/lo (A-side), K/V hi-only (B-side)
__device__ __half g_qh[BT*CC], g_ql[BT*CC];
__device__ __half g_kh[BT*CC];
__device__ __half g_vh[BT*CC];
__device__ __half g_wqh[HH*DD*CC];
__device__ __half g_wkh[HH*DD*CC];
__device__ __half g_wvh[HH*DD*CC];
__device__ __half g_whh[(size_t)C4*CC];
__device__ __half g_wph[(size_t)CC*C4];

__device__ __forceinline__ void split2h(float v, __half& hi, __half& lo) {
    hi = __float2half(v);
    lo = __float2half(v - __half2float(hi));
}

struct QKVOut {
    const __half *w0, *w1, *w2;
    __half *qh, *ql, *kh, *vh;
};

// ===================== transpose + fp16 round for weights ==================
// in fp32 [R, Cn] row-major -> out hi fp16 [Cn, R] (K-contiguous for MMA B)
__global__ __launch_bounds__(256) void tsplit_kernel(
    const float* __restrict__ in, __half* __restrict__ oh,
    int R, int Cn, long strideZ)
{
    __shared__ float ts[32][33];
    size_t zo = (size_t)blockIdx.z * strideZ;
    int r0 = blockIdx.y * 32, c0 = blockIdx.x * 32;
    int tx = threadIdx.x & 31, ty = threadIdx.x >> 5;
    #pragma unroll
    for (int i = 0; i < 4; i++) {
        int r = r0 + ty + i*8;
        ts[ty + i*8][tx] = in[zo + (size_t)r*Cn + c0 + tx];
    }
    __syncthreads();
    #pragma unroll
    for (int i = 0; i < 4; i++) {
        int cc = ty + i*8;
        size_t oi = zo + (size_t)(c0 + cc)*R + r0 + tx;
        oh[oi] = __float2half(ts[tx][cc]);
    }
}

// ===================== LayerNorm -> split fp16 (+opt residual) =============
template<bool ADD>
__global__ __launch_bounds__(256) void ln_kernel(
    const float* __restrict__ x, const float* __restrict__ add,
    const float* __restrict__ g, const float* __restrict__ be,
    __half* __restrict__ oh, __half* __restrict__ ol,
    float* __restrict__ outsum)
{
    int row = blockIdx.x;
    int tid = threadIdx.x;
    const float* xr = x + (size_t)row*CC;
    const float* ar = add + (size_t)row*CC;
    float v[3]; float s = 0.f, sq = 0.f;
    #pragma unroll
    for (int i = 0; i < 3; i++) {
        int c = tid + i*256;
        float val = xr[c];
        if (ADD) val += ar[c];
        v[i] = val; s += val; sq = fmaf(val, val, sq);
    }
    #pragma unroll
    for (int o = 16; o > 0; o >>= 1) {
        s  += __shfl_down_sync(0xffffffffu, s,  o);
        sq += __shfl_down_sync(0xffffffffu, sq, o);
    }
    __shared__ float rs[8], rq[8], stat[2];
    if ((tid & 31) == 0) { rs[tid>>5] = s; rq[tid>>5] = sq; }
    __syncthreads();
    if (tid == 0) {
        float ts = 0.f, tq = 0.f;
        #pragma unroll
        for (int i = 0; i < 8; i++) { ts += rs[i]; tq += rq[i]; }
        float mu  = ts * (1.0f/CC);
        float var = tq * (1.0f/CC) - mu*mu;
        stat[0] = mu; stat[1] = rsqrtf(var + 1e-5f);
    }
    __syncthreads();
    float mu = stat[0], rstd = stat[1];
    #pragma unroll
    for (int i = 0; i < 3; i++) {
        int c = tid + i*256;
        float val = (v[i]-mu)*rstd*g[c] + be[c];
        __half h, l; split2h(val, h, l);
        oh[(size_t)row*CC + c] = h;
        ol[(size_t)row*CC + c] = l;
        if (ADD) outsum[(size_t)row*CC + c] = v[i];
    }
}

// ===================== HMMA (mma.sync) GEMM =================================
// C[M,N] = A[M,K] * B[N,K]^T, fp16 2-term split: A(hi+lo) * B(hi).
// CTA tile 128 x NT, K-step 64, cp.async 2-stage pipeline, 256 threads.
// MODE 1: +bias, ReLU, store split fp16.  MODE 2: +bias +residual, f32 store.
// MODE 3: fused QKV: z = proj*HH + h; Q -> split hi/lo, K/V -> hi only,
//         out layout [B,H,T,D]. (Scale applied inside attention.)
template<int NT, int MODE>
__global__ __launch_bounds__(256)
void mm_kernel(
    const __half* __restrict__ Ah, const __half* __restrict__ Al,
    int lda, long strideA,
    const __half* __restrict__ Bh, long strideB,
    float* __restrict__ C, int ldc, long strideC,
    int Ktot,
    const float* __restrict__ bias, const float* __restrict__ res,
    __half* __restrict__ Oh, __half* __restrict__ Ol, int ldo,
    QKVOut qkv)
{
    static_assert(NT == 64 || NT == 128, "NT");
    constexpr int SA_H = 0;
    constexpr int SA_L = 16384;
    constexpr int SB_H = 32768;
    constexpr int STAGE = 32768 + NT*128;
    constexpr int NB = NT/32;
    constexpr int NW = NT/2;
    constexpr int NT8 = NW/8;
    constexpr int NT16 = NW/16;

    extern __shared__ char smraw[];
    char* sm = (char*)(((uintptr_t)smraw + 1023) & ~(uintptr_t)1023);
    uint32_t sm32 = smem_u32(sm);

    int tid = threadIdx.x;
    int wid = tid >> 5, lane = tid & 31;
    int z = blockIdx.z;
    int proj = 0, hsel = 0;
    if (MODE == 3) {
        proj = z / HH; hsel = z % HH;
        const __half* w = (proj == 0) ? qkv.w0 : (proj == 1) ? qkv.w1 : qkv.w2;
        Bh = w + (size_t)hsel*CC*DD;
    } else {
        Ah += (size_t)z * strideA;  Al += (size_t)z * strideA;
        Bh += (size_t)z * strideB;
        if (MODE == 2) C += (size_t)z * strideC;
    }
    int bm = blockIdx.y * 128, bn = blockIdx.x * NT;

    int wm = (wid & 3) * 32;
    int wn = (wid >> 2) * NW;

    int lr = lane & 7;
    int a_r = lr + ((lane & 8) ? 8 : 0);
    int a_k = (lane & 16) ? 16 : 0;
    int b_r = lr + ((lane & 16) ? 8 : 0);
    int b_k = (lane & 8) ? 16 : 0;

    int g_row = tid >> 3, g_ch = tid & 7;

    float acc[2][NT8][4];
    #pragma unroll
    for (int mt = 0; mt < 2; mt++)
        #pragma unroll
        for (int nt = 0; nt < NT8; nt++)
            #pragma unroll
            for (int j = 0; j < 4; j++) acc[mt][nt][j] = 0.f;

    int nk = Ktot >> 6;

    auto load_stage = [&](int t) {
        int stg = (t & 1) * STAGE;
        int k0 = t << 6;
        #pragma unroll
        for (int i = 0; i < 4; i++) {
            int row = g_row + i*32;
            uint32_t so = sm32 + stg + SWZ(row*128 + g_ch*16);
            CP16(so + SA_H, Ah + (size_t)(bm+row)*lda + k0 + g_ch*8);
            CP16(so + SA_L, Al + (size_t)(bm+row)*lda + k0 + g_ch*8);
        }
        #pragma unroll
        for (int i = 0; i < NB; i++) {
            int row = g_row + i*32;
            uint32_t so = sm32 + stg + SWZ(row*128 + g_ch*16);
            CP16(so + SB_H, Bh + (size_t)(bn+row)*lda + k0 + g_ch*8);
        }
        CP_COMMIT();
    };

    load_stage(0);
    if (nk > 1) load_stage(1);

    for (int t = 0; t < nk; t++) {
        if (t < nk - 1) { CP_WAIT(1); } else { CP_WAIT(0); }
        __syncthreads();
        int stg = (t & 1) * STAGE;
        uint32_t baseA_h = sm32 + stg + SA_H;
        uint32_t baseA_l = sm32 + stg + SA_L;
        uint32_t baseB_h = sm32 + stg + SB_H;

        #pragma unroll
        for (int kt = 0; kt < 4; kt++) {
            int kb = kt*32;
            uint32_t ah[2][4], al[2][4];
            #pragma unroll
            for (int mt = 0; mt < 2; mt++) {
                uint32_t off = SWZ((wm + mt*16 + a_r)*128 + kb + a_k);
                LDSM_X4(ah[mt][0], ah[mt][1], ah[mt][2], ah[mt][3], baseA_h + off);
                LDSM_X4(al[mt][0], al[mt][1], al[mt][2], al[mt][3], baseA_l + off);
            }
            uint32_t bh[NT16][4];
            #pragma unroll
            for (int n2 = 0; n2 < NT16; n2++) {
                uint32_t off = SWZ((wn + n2*16 + b_r)*128 + kb + b_k);
                LDSM_X4(bh[n2][0], bh[n2][1], bh[n2][2], bh[n2][3], baseB_h + off);
            }
            #pragma unroll
            for (int mt = 0; mt < 2; mt++) {
                #pragma unroll
                for (int n2 = 0; n2 < NT16; n2++) {
                    MMA_F16(acc[mt][n2*2],   ah[mt], bh[n2][0], bh[n2][1]);
                    MMA_F16(acc[mt][n2*2+1], ah[mt], bh[n2][2], bh[n2][3]);
                    MMA_F16(acc[mt][n2*2],   al[mt], bh[n2][0], bh[n2][1]);
                    MMA_F16(acc[mt][n2*2+1], al[mt], bh[n2][2], bh[n2][3]);
                }
            }
        }
        __syncthreads();
        if (t + 2 < nk) load_stage(t + 2);
    }

    // ---- epilogue ----
    int mrow0 = bm + wm + (lane >> 2);
    int ncol0 = bn + wn + (lane & 3) * 2;
    #pragma unroll
    for (int mt = 0; mt < 2; mt++) {
        #pragma unroll
        for (int half = 0; half < 2; half++) {
            int m = mrow0 + mt*16 + half*8;
            #pragma unroll
            for (int nt = 0; nt < NT8; nt++) {
                int n = ncol0 + nt*8;
                float v0 = acc[mt][nt][half*2];
                float v1 = acc[mt][nt][half*2+1];
                if (MODE == 1) {
                    v0 = fmaxf(v0 + bias[n],   0.f);
                    v1 = fmaxf(v1 + bias[n+1], 0.f);
                    __half h0, l0, h1, l1;
                    split2h(v0, h0, l0); split2h(v1, h1, l1);
                    __half2 hh2; hh2.x = h0; hh2.y = h1;
                    __half2 ll2; ll2.x = l0; ll2.y = l1;
                    *(__half2*)(Oh + (size_t)m*ldo + n) = hh2;
                    *(__half2*)(Ol + (size_t)m*ldo + n) = ll2;
                } else if (MODE == 2) {
                    float2 rr = *(const float2*)(res + (size_t)m*ldc + n);
                    float2 o;
                    o.x = v0 + bias[n]   + rr.x;
                    o.y = v1 + bias[n+1] + rr.y;
                    *(float2*)(C + (size_t)m*ldc + n) = o;
                } else if (MODE == 3) {
                    int bidx = m >> 11, tt = m & (TT-1);
                    size_t o = (((size_t)bidx*HH + hsel)*TT + tt)*DD + n;
                    if (proj == 0) {
                        __half h0, l0, h1, l1;
                        split2h(v0, h0, l0); split2h(v1, h1, l1);
                        __half2 hh2; hh2.x = h0; hh2.y = h1;
                        __half2 ll2; ll2.x = l0; ll2.y = l1;
                        *(__half2*)(qkv.qh + o) = hh2;
                        *(__half2*)(qkv.ql + o) = ll2;
                    } else {
                        __half2 hh2;
                        hh2.x = __float2half(v0); hh2.y = __float2half(v1);
                        __half* p = (proj == 1) ? qkv.kh : qkv.vh;
                        *(__half2*)(p + o) = hh2;
                    }
                }
            }
        }
    }
}

// ===================== HMMA flash attention (causal) ========================
// grid (32, 24) reversed-qt, 128 threads (4 warps), warp owns 16 q rows.
// fp16: Q split hi/lo (A-side), K/V hi-only (B-side); P split hi/lo.
// Scores scaled by SCALE post-MMA.
__global__ __launch_bounds__(128) void attn_kernel(
    const __half* __restrict__ Qh, const __half* __restrict__ Ql,
    const __half* __restrict__ Kh, const __half* __restrict__ Vh,
    float* __restrict__ O)
{
    extern __shared__ char smraw[];
    char* sm = (char*)(((uintptr_t)smraw + 1023) & ~(uintptr_t)1023);
    uint32_t sm32 = smem_u32(sm);

    constexpr int QH_O = 0, QL_O = 8192, STG_O = 16384, STG_SZ = 16384;
    // in-stage: KH +0, VH +8192

    int qt = gridDim.x - 1 - (int)blockIdx.x;   // longest first
    int bh = blockIdx.y;
    int b = bh / HH, h = bh % HH;
    int tid = threadIdx.x, wid = tid >> 5, lane = tid & 31;
    size_t base = (size_t)bh * TT * DD;

    // ---- issue Q loads (part of group 0) ----
    #pragma unroll
    for (int i = 0; i < 4; i++) {
        int idx = tid + i*128; int row = idx >> 3, ch = idx & 7;
        uint32_t so = sm32 + SWZ(row*128 + ch*16);
        size_t ga = base + (size_t)(qt*64 + row)*DD + ch*8;
        CP16(so + QH_O, Qh + ga);
        CP16(so + QL_O, Ql + ga);
    }
    auto load_kv = [&](int kt) {
        int stg = STG_O + (kt & 1) * STG_SZ;
        #pragma unroll
        for (int i = 0; i < 4; i++) {
            int idx = tid + i*128; int row = idx >> 3, ch = idx & 7;
            uint32_t so = sm32 + stg + SWZ(row*128 + ch*16);
            size_t ga = base + (size_t)(kt*64 + row)*DD + ch*8;
            CP16(so,        Kh + ga);
            CP16(so + 8192, Vh + ga);
        }
        CP_COMMIT();
    };
    load_kv(0);                 // group 0 (includes Q)
    if (qt >= 1) load_kv(1);    // group 1

    int lr = lane & 7;
    int a_r = lr + ((lane & 8) ? 8 : 0);
    int a_k = (lane & 16) ? 16 : 0;
    int b_r = lr + ((lane & 16) ? 8 : 0);
    int b_k = (lane & 8) ? 16 : 0;
    int v_r = lr + ((lane & 8) ? 8 : 0);    // trans (V) addressing
    int v_k = (lane & 16) ? 16 : 0;
    int wm = wid * 16;

    float o[8][4];
    #pragma unroll
    for (int nf = 0; nf < 8; nf++)
        #pragma unroll
        for (int j = 0; j < 4; j++) o[nf][j] = 0.f;
    float mrow0 = -1e30f, mrow1 = -1e30f, lrow0 = 0.f, lrow1 = 0.f;

    if (qt >= 1) { CP_WAIT(1); } else { CP_WAIT(0); }
    __syncthreads();

    // Q fragments resident in registers for the whole kernel
    uint32_t qhf[4][4], qlf[4][4];
    #pragma unroll
    for (int kc = 0; kc < 4; kc++) {
        uint32_t off = SWZ((wm + a_r)*128 + kc*32 + a_k);
        LDSM_X4(qhf[kc][0], qhf[kc][1], qhf[kc][2], qhf[kc][3], sm32 + QH_O + off);
        LDSM_X4(qlf[kc][0], qlf[kc][1], qlf[kc][2], qlf[kc][3], sm32 + QL_O + off);
    }

    for (int kt = 0; kt <= qt; kt++) {
        if (kt > 0) {
            if (kt < qt) { CP_WAIT(1); } else { CP_WAIT(0); }
            __syncthreads();
        }
        uint32_t kbh = sm32 + STG_O + (kt & 1)*STG_SZ;
        uint32_t vbh = kbh + 8192;

        // ---- S = Q K^T (2-term fp16) ----
        float s[8][4];
        #pragma unroll
        for (int nf = 0; nf < 8; nf++)
            #pragma unroll
            for (int j = 0; j < 4; j++) s[nf][j] = 0.f;

        #pragma unroll
        for (int kc = 0; kc < 4; kc++) {
            #pragma unroll
            for (int c2 = 0; c2 < 4; c2++) {
                uint32_t h4[4];
                uint32_t off = SWZ((c2*16 + b_r)*128 + kc*32 + b_k);
                LDSM_X4(h4[0], h4[1], h4[2], h4[3], kbh + off);
                MMA_F16(s[c2*2],   qhf[kc], h4[0], h4[1]);
                MMA_F16(s[c2*2+1], qhf[kc], h4[2], h4[3]);
                MMA_F16(s[c2*2],   qlf[kc], h4[0], h4[1]);
                MMA_F16(s[c2*2+1], qlf[kc], h4[2], h4[3]);
            }
        }

        // ---- scale + causal mask on diagonal tile ----
        #pragma unroll
        for (int nf = 0; nf < 8; nf++)
            #pragma unroll
            for (int j = 0; j < 4; j++) s[nf][j] *= SCALE;
        if (kt == qt) {
            int r0 = wm + (lane >> 2), r1 = r0 + 8;
            #pragma unroll
            for (int nf = 0; nf < 8; nf++) {
                int c = nf*8 + (lane & 3)*2;
                if (c   > r0) s[nf][0] = -1e30f;
                if (c+1 > r0) s[nf][1] = -1e30f;
                if (c   > r1) s[nf][2] = -1e30f;
                if (c+1 > r1) s[nf][3] = -1e30f;
            }
        }

        // ---- online softmax (register-only, quad shfl reduction) ----
        float t0 = -1e30f, t1 = -1e30f;
        #pragma unroll
        for (int nf = 0; nf < 8; nf++) {
            t0 = fmaxf(t0, fmaxf(s[nf][0], s[nf][1]));
            t1 = fmaxf(t1, fmaxf(s[nf][2], s[nf][3]));
        }
        t0 = fmaxf(t0, __shfl_xor_sync(0xffffffffu, t0, 1));
        t0 = fmaxf(t0, __shfl_xor_sync(0xffffffffu, t0, 2));
        t1 = fmaxf(t1, __shfl_xor_sync(0xffffffffu, t1, 1));
        t1 = fmaxf(t1, __shfl_xor_sync(0xffffffffu, t1, 2));
        float mn0 = fmaxf(mrow0, t0), mn1 = fmaxf(mrow1, t1);
        float al0 = __expf(mrow0 - mn0), al1 = __expf(mrow1 - mn1);
        mrow0 = mn0; mrow1 = mn1;
        float ps0 = 0.f, ps1 = 0.f;
        #pragma unroll
        for (int nf = 0; nf < 8; nf++) {
            s[nf][0] = __expf(s[nf][0] - mn0);
            s[nf][1] = __expf(s[nf][1] - mn0);
            s[nf][2] = __expf(s[nf][2] - mn1);
            s[nf][3] = __expf(s[nf][3] - mn1);
            ps0 += s[nf][0] + s[nf][1];
            ps1 += s[nf][2] + s[nf][3];
        }
        ps0 += __shfl_xor_sync(0xffffffffu, ps0, 1);
        ps0 += __shfl_xor_sync(0xffffffffu, ps0, 2);
        ps1 += __shfl_xor_sync(0xffffffffu, ps1, 1);
        ps1 += __shfl_xor_sync(0xffffffffu, ps1, 2);
        lrow0 = lrow0*al0 + ps0;
        lrow1 = lrow1*al1 + ps1;
        #pragma unroll
        for (int nf = 0; nf < 8; nf++) {
            o[nf][0] *= al0; o[nf][1] *= al0;
            o[nf][2] *= al1; o[nf][3] *= al1;
        }

        // ---- O += P V (2-term; P D-frags -> A-frags in registers) ----
        #pragma unroll
        for (int sk = 0; sk < 4; sk++) {
            int f0 = sk*2, f1 = sk*2+1;
            uint32_t pha[4], pla[4];
            pha[0] = pack_h2(s[f0][0], s[f0][1]);
            pha[1] = pack_h2(s[f0][2], s[f0][3]);
            pha[2] = pack_h2(s[f1][0], s[f1][1]);
            pha[3] = pack_h2(s[f1][2], s[f1][3]);
            float2 u0 = unpack_h2(pha[0]);
            float2 u1 = unpack_h2(pha[1]);
            float2 u2 = unpack_h2(pha[2]);
            float2 u3 = unpack_h2(pha[3]);
            pla[0] = pack_h2(s[f0][0]-u0.x, s[f0][1]-u0.y);
            pla[1] = pack_h2(s[f0][2]-u1.x, s[f0][3]-u1.y);
            pla[2] = pack_h2(s[f1][0]-u2.x, s[f1][1]-u2.y);
            pla[3] = pack_h2(s[f1][2]-u3.x, s[f1][3]-u3.y);
            #pragma unroll
            for (int c2 = 0; c2 < 4; c2++) {
                uint32_t vh4[4];
                uint32_t off = SWZ((sk*16 + v_r)*128 + c2*32 + v_k);
                LDSM_X4T(vh4[0], vh4[1], vh4[2], vh4[3], vbh + off);
                MMA_F16(o[c2*2],   pha, vh4[0], vh4[1]);
                MMA_F16(o[c2*2+1], pha, vh4[2], vh4[3]);
                MMA_F16(o[c2*2],   pla, vh4[0], vh4[1]);
                MMA_F16(o[c2*2+1], pla, vh4[2], vh4[3]);
            }
        }

        __syncthreads();
        if (kt + 2 <= qt) load_kv(kt + 2);
    }

    // ---- epilogue: O / l, write f32 [B,T,C] ----
    float inv0 = 1.0f / lrow0, inv1 = 1.0f / lrow1;
    int r0 = qt*64 + wm + (lane >> 2), r1 = r0 + 8;
    size_t ob = (size_t)b * TT;
    #pragma unroll
    for (int nf = 0; nf < 8; nf++) {
        int d = nf*8 + (lane & 3)*2;
        float2 w0; w0.x = o[nf][0]*inv0; w0.y = o[nf][1]*inv0;
        float2 w1; w1.x = o[nf][2]*inv1; w1.y = o[nf][3]*inv1;
        *(float2*)(O + (ob + r0)*CC + h*DD + d) = w0;
        *(float2*)(O + (ob + r1)*CC + h*DD + d) = w1;
    }
}

#define ATTN_SMEM (1024 + 16384 + 2*16384)
#define MM_SMEM(NT) (1024 + 2*(32768 + (NT)*128))

// ===================== launch ===============================================
extern "C" void kernel_launch(void* const* d_in, const int* in_sizes, int n_in,
                              void* d_out, int out_size)
{
    const float* x    = (const float*)d_in[0];
    const float* ln1g = (const float*)d_in[1];
    const float* ln1b = (const float*)d_in[2];
    const float* wq   = (const float*)d_in[3];
    const float* wk   = (const float*)d_in[4];
    const float* wv   = (const float*)d_in[5];
    const float* ln2g = (const float*)d_in[6];
    const float* ln2b = (const float*)d_in[7];
    const float* wh   = (const float*)d_in[8];
    const float* bh   = (const float*)d_in[9];
    const float* wp   = (const float*)d_in[10];
    const float* bp   = (const float*)d_in[11];
    float* out = (float*)d_out;

    float *att, *x1;
    __half *hh, *hl, *h2h, *h2l, *hidh, *hidl;
    __half *qh, *ql, *kh, *vh;
    __half *wqh, *wkh, *wvh, *whh, *wph;
    cudaGetSymbolAddress((void**)&att,  g_att);
    cudaGetSymbolAddress((void**)&x1,   g_x1);
    cudaGetSymbolAddress((void**)&hh,   g_hh);
    cudaGetSymbolAddress((void**)&hl,   g_hl);
    cudaGetSymbolAddress((void**)&h2h,  g_h2h);
    cudaGetSymbolAddress((void**)&h2l,  g_h2l);
    cudaGetSymbolAddress((void**)&hidh, g_hidh);
    cudaGetSymbolAddress((void**)&hidl, g_hidl);
    cudaGetSymbolAddress((void**)&qh,   g_qh);
    cudaGetSymbolAddress((void**)&ql,   g_ql);
    cudaGetSymbolAddress((void**)&kh,   g_kh);
    cudaGetSymbolAddress((void**)&vh,   g_vh);
    cudaGetSymbolAddress((void**)&wqh,  g_wqh);
    cudaGetSymbolAddress((void**)&wkh,  g_wkh);
    cudaGetSymbolAddress((void**)&wvh,  g_wvh);
    cudaGetSymbolAddress((void**)&whh,  g_whh);
    cudaGetSymbolAddress((void**)&wph,  g_wph);

    cudaFuncSetAttribute(attn_kernel,
        cudaFuncAttributeMaxDynamicSharedMemorySize, ATTN_SMEM);
    cudaFuncSetAttribute(mm_kernel<64,3>,
        cudaFuncAttributeMaxDynamicSharedMemorySize, MM_SMEM(64));
    cudaFuncSetAttribute(mm_kernel<128,1>,
        cudaFuncAttributeMaxDynamicSharedMemorySize, MM_SMEM(128));
    cudaFuncSetAttribute(mm_kernel<128,2>,
        cudaFuncAttributeMaxDynamicSharedMemorySize, MM_SMEM(128));

    // weight prep: transpose + fp16 round (hi only; B-side residual dropped)
    tsplit_kernel<<<dim3(2, 24, HH), 256>>>(wq, wqh, CC, DD, (long)CC*DD);
    tsplit_kernel<<<dim3(2, 24, HH), 256>>>(wk, wkh, CC, DD, (long)CC*DD);
    tsplit_kernel<<<dim3(2, 24, HH), 256>>>(wv, wvh, CC, DD, (long)CC*DD);
    tsplit_kernel<<<dim3(96, 24, 1), 256>>>(wh, whh, CC, C4, 0);
    tsplit_kernel<<<dim3(24, 96, 1), 256>>>(wp, wph, C4, CC, 0);

    // LN1 -> split fp16
    ln_kernel<false><<<BT, 256>>>(x, x, ln1g, ln1b, hh, hl, nullptr);

    // fused QKV projection (z = proj*HH + h), out fp16 [B,H,T,D]
    QKVOut qkv;
    qkv.w0 = wqh; qkv.w1 = wkh; qkv.w2 = wvh;
    qkv.qh = qh; qkv.ql = ql; qkv.kh = kh; qkv.vh = vh;
    QKVOut qkv0 = {};
    mm_kernel<64,3><<<dim3(1, BT/128, 3*HH), 256, MM_SMEM(64)>>>(
        hh, hl, CC, 0, nullptr, 0,
        nullptr, 0, 0, CC, nullptr, nullptr, nullptr, nullptr, 0, qkv);

    // HMMA flash attention
    attn_kernel<<<dim3(TT/64, BB*HH), 128, ATTN_SMEM>>>(qh, ql, kh, vh, att);

    // residual + LN2 -> split fp16 (+x1)
    ln_kernel<true><<<BT, 256>>>(x, att, ln2g, ln2b, h2h, h2l, x1);

    // MLP (HMMA)
    mm_kernel<128,1><<<dim3(C4/128, BT/128, 1), 256, MM_SMEM(128)>>>(
        h2h, h2l, CC, 0, whh, 0, nullptr, 0, 0, CC, bh, nullptr,
        hidh, hidl, C4, qkv0);
    mm_kernel<128,2><<<dim3(CC/128, BT/128, 1), 256, MM_SMEM(128)>>>(
        hidh, hidl, C4, 0, wph, 0, out, CC, 0, C4, bp, x1,
        nullptr, nullptr, 0, qkv0);
}

// round 6
// speedup vs baseline: 4.8256x; 1.0660x over previous
#include <cuda_runtime.h>
#include <cuda_fp16.h>
#include <cstdint>

#define BB 2
#define TT 2048
#define CC 768
#define HH 12
#define DD 64
#define BT (BB*TT)          // 4096 rows
#define C4 (4*CC)           // 3072
#define SCALE 0.03608439182435161f           // 1/sqrt(768)
#define SCALE_L2E (0.03608439182435161f * 1.4426950408889634f)  // log2 domain

// ===================== PTX helpers (sm_80-compatible only) ==================
__device__ __forceinline__ uint32_t smem_u32(const void* p) {
    uint32_t a;
    asm("{ .reg .u64 t; cvta.to.shared.u64 t, %1; cvt.u32.u64 %0, t; }"
        : "=r"(a) : "l"(p));
    return a;
}

#define CP16(s, g) \
    asm volatile("cp.async.cg.shared.global [%0], [%1], 16;" :: "r"(s), "l"(g))
#define CP_COMMIT() asm volatile("cp.async.commit_group;" ::: "memory")
#define CP_WAIT(n)  asm volatile("cp.async.wait_group %0;" :: "n"(n) : "memory")

#define LDSM_X4(r0, r1, r2, r3, a) \
    asm volatile("ldmatrix.sync.aligned.m8n8.x4.shared.b16 {%0,%1,%2,%3}, [%4];" \
        : "=r"(r0), "=r"(r1), "=r"(r2), "=r"(r3) : "r"(a))

#define LDSM_X4T(r0, r1, r2, r3, a) \
    asm volatile("ldmatrix.sync.aligned.m8n8.x4.trans.shared.b16 {%0,%1,%2,%3}, [%4];" \
        : "=r"(r0), "=r"(r1), "=r"(r2), "=r"(r3) : "r"(a))

#define MMA_F16(d, a, b0, b1) \
    asm volatile("mma.sync.aligned.m16n8k16.row.col.f32.f16.f16.f32 " \
        "{%0,%1,%2,%3}, {%4,%5,%6,%7}, {%8,%9}, {%0,%1,%2,%3};" \
        : "+f"((d)[0]), "+f"((d)[1]), "+f"((d)[2]), "+f"((d)[3]) \
        : "r"((a)[0]), "r"((a)[1]), "r"((a)[2]), "r"((a)[3]), "r"(b0), "r"(b1))

#define SWZ(x) ((x) ^ (((x) >> 3) & 0x70))

__device__ __forceinline__ uint32_t pack_h2(float lo, float hi) {
    uint32_t r;
    asm("cvt.rn.f16x2.f32 %0, %1, %2;" : "=r"(r) : "f"(hi), "f"(lo));
    return r;
}
__device__ __forceinline__ uint32_t hexp2_2(uint32_t a) {
    uint32_t r;
    asm("ex2.approx.f16x2 %0, %1;" : "=r"(r) : "r"(a));
    return r;
}
__device__ __forceinline__ float fexp2(float x) {
    float r;
    asm("ex2.approx.ftz.f32 %0, %1;" : "=f"(r) : "f"(x));
    return r;
}

// ===================== scratch (static device memory) ======================
__device__ float g_att[BT*CC];
__device__ float g_x1 [BT*CC];
__device__ __half g_hh [BT*CC],  g_hl [BT*CC];
__device__ __half g_h2h[BT*CC],  g_h2l[BT*CC];
__device__ __half g_hidh[(size_t)BT*C4], g_hidl[(size_t)BT*C4];
// qkv, layout [B,H,T,D]; Q split hi/lo (A-side), K/V hi-only (B-side)
__device__ __half g_qh[BT*CC], g_ql[BT*CC];
__device__ __half g_kh[BT*CC];
__device__ __half g_vh[BT*CC];
__device__ __half g_wqh[HH*DD*CC];
__device__ __half g_wkh[HH*DD*CC];
__device__ __half g_wvh[HH*DD*CC];
__device__ __half g_whh[(size_t)C4*CC];
__device__ __half g_wph[(size_t)CC*C4];

__device__ __forceinline__ void split2h(float v, __half& hi, __half& lo) {
    hi = __float2half(v);
    lo = __float2half(v - __half2float(hi));
}

struct QKVOut {
    const __half *w0, *w1, *w2;
    __half *qh, *ql, *kh, *vh;
};

// ===================== transpose + fp16 round for weights ==================
__global__ __launch_bounds__(256) void tsplit_kernel(
    const float* __restrict__ in, __half* __restrict__ oh,
    int R, int Cn, long strideZ)
{
    __shared__ float ts[32][33];
    size_t zo = (size_t)blockIdx.z * strideZ;
    int r0 = blockIdx.y * 32, c0 = blockIdx.x * 32;
    int tx = threadIdx.x & 31, ty = threadIdx.x >> 5;
    #pragma unroll
    for (int i = 0; i < 4; i++) {
        int r = r0 + ty + i*8;
        ts[ty + i*8][tx] = in[zo + (size_t)r*Cn + c0 + tx];
    }
    __syncthreads();
    #pragma unroll
    for (int i = 0; i < 4; i++) {
        int cc = ty + i*8;
        size_t oi = zo + (size_t)(c0 + cc)*R + r0 + tx;
        oh[oi] = __float2half(ts[tx][cc]);
    }
}

// ===================== LayerNorm -> split fp16 (+opt residual) =============
template<bool ADD>
__global__ __launch_bounds__(256) void ln_kernel(
    const float* __restrict__ x, const float* __restrict__ add,
    const float* __restrict__ g, const float* __restrict__ be,
    __half* __restrict__ oh, __half* __restrict__ ol,
    float* __restrict__ outsum)
{
    int row = blockIdx.x;
    int tid = threadIdx.x;
    const float* xr = x + (size_t)row*CC;
    const float* ar = add + (size_t)row*CC;
    float v[3]; float s = 0.f, sq = 0.f;
    #pragma unroll
    for (int i = 0; i < 3; i++) {
        int c = tid + i*256;
        float val = xr[c];
        if (ADD) val += ar[c];
        v[i] = val; s += val; sq = fmaf(val, val, sq);
    }
    #pragma unroll
    for (int o = 16; o > 0; o >>= 1) {
        s  += __shfl_down_sync(0xffffffffu, s,  o);
        sq += __shfl_down_sync(0xffffffffu, sq, o);
    }
    __shared__ float rs[8], rq[8], stat[2];
    if ((tid & 31) == 0) { rs[tid>>5] = s; rq[tid>>5] = sq; }
    __syncthreads();
    if (tid == 0) {
        float ts = 0.f, tq = 0.f;
        #pragma unroll
        for (int i = 0; i < 8; i++) { ts += rs[i]; tq += rq[i]; }
        float mu  = ts * (1.0f/CC);
        float var = tq * (1.0f/CC) - mu*mu;
        stat[0] = mu; stat[1] = rsqrtf(var + 1e-5f);
    }
    __syncthreads();
    float mu = stat[0], rstd = stat[1];
    #pragma unroll
    for (int i = 0; i < 3; i++) {
        int c = tid + i*256;
        float val = (v[i]-mu)*rstd*g[c] + be[c];
        __half h, l; split2h(val, h, l);
        oh[(size_t)row*CC + c] = h;
        ol[(size_t)row*CC + c] = l;
        if (ADD) outsum[(size_t)row*CC + c] = v[i];
    }
}

// ===================== HMMA (mma.sync) GEMM =================================
// C[M,N] = A[M,K] * B[N,K]^T, fp16 2-term split: A(hi+lo) * B(hi).
// MODE 1: +bias, ReLU, store split fp16.  MODE 2: +bias +residual, f32 store.
// MODE 3: fused QKV (z = proj*HH + h), out [B,H,T,D].
template<int NT, int MODE>
__global__ __launch_bounds__(256)
void mm_kernel(
    const __half* __restrict__ Ah, const __half* __restrict__ Al,
    int lda, long strideA,
    const __half* __restrict__ Bh, long strideB,
    float* __restrict__ C, int ldc, long strideC,
    int Ktot,
    const float* __restrict__ bias, const float* __restrict__ res,
    __half* __restrict__ Oh, __half* __restrict__ Ol, int ldo,
    QKVOut qkv)
{
    static_assert(NT == 64 || NT == 128, "NT");
    constexpr int SA_H = 0;
    constexpr int SA_L = 16384;
    constexpr int SB_H = 32768;
    constexpr int STAGE = 32768 + NT*128;
    constexpr int NB = NT/32;
    constexpr int NW = NT/2;
    constexpr int NT8 = NW/8;
    constexpr int NT16 = NW/16;

    extern __shared__ char smraw[];
    char* sm = (char*)(((uintptr_t)smraw + 1023) & ~(uintptr_t)1023);
    uint32_t sm32 = smem_u32(sm);

    int tid = threadIdx.x;
    int wid = tid >> 5, lane = tid & 31;
    int z = blockIdx.z;
    int proj = 0, hsel = 0;
    if (MODE == 3) {
        proj = z / HH; hsel = z % HH;
        const __half* w = (proj == 0) ? qkv.w0 : (proj == 1) ? qkv.w1 : qkv.w2;
        Bh = w + (size_t)hsel*CC*DD;
    } else {
        Ah += (size_t)z * strideA;  Al += (size_t)z * strideA;
        Bh += (size_t)z * strideB;
        if (MODE == 2) C += (size_t)z * strideC;
    }
    int bm = blockIdx.y * 128, bn = blockIdx.x * NT;

    int wm = (wid & 3) * 32;
    int wn = (wid >> 2) * NW;

    int lr = lane & 7;
    int a_r = lr + ((lane & 8) ? 8 : 0);
    int a_k = (lane & 16) ? 16 : 0;
    int b_r = lr + ((lane & 16) ? 8 : 0);
    int b_k = (lane & 8) ? 16 : 0;

    int g_row = tid >> 3, g_ch = tid & 7;

    float acc[2][NT8][4];
    #pragma unroll
    for (int mt = 0; mt < 2; mt++)
        #pragma unroll
        for (int nt = 0; nt < NT8; nt++)
            #pragma unroll
            for (int j = 0; j < 4; j++) acc[mt][nt][j] = 0.f;

    int nk = Ktot >> 6;

    auto load_stage = [&](int t) {
        int stg = (t & 1) * STAGE;
        int k0 = t << 6;
        #pragma unroll
        for (int i = 0; i < 4; i++) {
            int row = g_row + i*32;
            uint32_t so = sm32 + stg + SWZ(row*128 + g_ch*16);
            CP16(so + SA_H, Ah + (size_t)(bm+row)*lda + k0 + g_ch*8);
            CP16(so + SA_L, Al + (size_t)(bm+row)*lda + k0 + g_ch*8);
        }
        #pragma unroll
        for (int i = 0; i < NB; i++) {
            int row = g_row + i*32;
            uint32_t so = sm32 + stg + SWZ(row*128 + g_ch*16);
            CP16(so + SB_H, Bh + (size_t)(bn+row)*lda + k0 + g_ch*8);
        }
        CP_COMMIT();
    };

    load_stage(0);
    if (nk > 1) load_stage(1);

    for (int t = 0; t < nk; t++) {
        if (t < nk - 1) { CP_WAIT(1); } else { CP_WAIT(0); }
        __syncthreads();
        int stg = (t & 1) * STAGE;
        uint32_t baseA_h = sm32 + stg + SA_H;
        uint32_t baseA_l = sm32 + stg + SA_L;
        uint32_t baseB_h = sm32 + stg + SB_H;

        #pragma unroll
        for (int kt = 0; kt < 4; kt++) {
            int kb = kt*32;
            uint32_t ah[2][4], al[2][4];
            #pragma unroll
            for (int mt = 0; mt < 2; mt++) {
                uint32_t off = SWZ((wm + mt*16 + a_r)*128 + kb + a_k);
                LDSM_X4(ah[mt][0], ah[mt][1], ah[mt][2], ah[mt][3], baseA_h + off);
                LDSM_X4(al[mt][0], al[mt][1], al[mt][2], al[mt][3], baseA_l + off);
            }
            uint32_t bh[NT16][4];
            #pragma unroll
            for (int n2 = 0; n2 < NT16; n2++) {
                uint32_t off = SWZ((wn + n2*16 + b_r)*128 + kb + b_k);
                LDSM_X4(bh[n2][0], bh[n2][1], bh[n2][2], bh[n2][3], baseB_h + off);
            }
            #pragma unroll
            for (int mt = 0; mt < 2; mt++) {
                #pragma unroll
                for (int n2 = 0; n2 < NT16; n2++) {
                    MMA_F16(acc[mt][n2*2],   ah[mt], bh[n2][0], bh[n2][1]);
                    MMA_F16(acc[mt][n2*2+1], ah[mt], bh[n2][2], bh[n2][3]);
                    MMA_F16(acc[mt][n2*2],   al[mt], bh[n2][0], bh[n2][1]);
                    MMA_F16(acc[mt][n2*2+1], al[mt], bh[n2][2], bh[n2][3]);
                }
            }
        }
        __syncthreads();
        if (t + 2 < nk) load_stage(t + 2);
    }

    // ---- epilogue ----
    int mrow0 = bm + wm + (lane >> 2);
    int ncol0 = bn + wn + (lane & 3) * 2;
    #pragma unroll
    for (int mt = 0; mt < 2; mt++) {
        #pragma unroll
        for (int half = 0; half < 2; half++) {
            int m = mrow0 + mt*16 + half*8;
            #pragma unroll
            for (int nt = 0; nt < NT8; nt++) {
                int n = ncol0 + nt*8;
                float v0 = acc[mt][nt][half*2];
                float v1 = acc[mt][nt][half*2+1];
                if (MODE == 1) {
                    v0 = fmaxf(v0 + bias[n],   0.f);
                    v1 = fmaxf(v1 + bias[n+1], 0.f);
                    __half h0, l0, h1, l1;
                    split2h(v0, h0, l0); split2h(v1, h1, l1);
                    __half2 hh2; hh2.x = h0; hh2.y = h1;
                    __half2 ll2; ll2.x = l0; ll2.y = l1;
                    *(__half2*)(Oh + (size_t)m*ldo + n) = hh2;
                    *(__half2*)(Ol + (size_t)m*ldo + n) = ll2;
                } else if (MODE == 2) {
                    float2 rr = *(const float2*)(res + (size_t)m*ldc + n);
                    float2 o;
                    o.x = v0 + bias[n]   + rr.x;
                    o.y = v1 + bias[n+1] + rr.y;
                    *(float2*)(C + (size_t)m*ldc + n) = o;
                } else if (MODE == 3) {
                    int bidx = m >> 11, tt = m & (TT-1);
                    size_t o = (((size_t)bidx*HH + hsel)*TT + tt)*DD + n;
                    if (proj == 0) {
                        __half h0, l0, h1, l1;
                        split2h(v0, h0, l0); split2h(v1, h1, l1);
                        __half2 hh2; hh2.x = h0; hh2.y = h1;
                        __half2 ll2; ll2.x = l0; ll2.y = l1;
                        *(__half2*)(qkv.qh + o) = hh2;
                        *(__half2*)(qkv.ql + o) = ll2;
                    } else {
                        __half2 hh2;
                        hh2.x = __float2half(v0); hh2.y = __float2half(v1);
                        __half* p = (proj == 1) ? qkv.kh : qkv.vh;
                        *(__half2*)(p + o) = hh2;
                    }
                }
            }
        }
    }
}

// ===================== HMMA flash attention (causal) ========================
// 128 threads (4 warps), warp owns 16 q rows. Softmax in log2 domain with
// f16x2 ex2 (2 exps / MUFU op). P consumed directly as fp16 A-fragments.
// Row sums via all-ones constant B-fragment MMA (rides the tensor pipe).
__global__ __launch_bounds__(128) void attn_kernel(
    const __half* __restrict__ Qh, const __half* __restrict__ Ql,
    const __half* __restrict__ Kh, const __half* __restrict__ Vh,
    float* __restrict__ O)
{
    extern __shared__ char smraw[];
    char* sm = (char*)(((uintptr_t)smraw + 1023) & ~(uintptr_t)1023);
    uint32_t sm32 = smem_u32(sm);

    constexpr int QH_O = 0, QL_O = 8192, STG_O = 16384, STG_SZ = 16384;
    constexpr uint32_t ONE2 = 0x3C003C00u;   // half2(1.0, 1.0)

    int qt = gridDim.x - 1 - (int)blockIdx.x;   // longest first
    int bh = blockIdx.y;
    int b = bh / HH, h = bh % HH;
    int tid = threadIdx.x, wid = tid >> 5, lane = tid & 31;
    size_t base = (size_t)bh * TT * DD;

    #pragma unroll
    for (int i = 0; i < 4; i++) {
        int idx = tid + i*128; int row = idx >> 3, ch = idx & 7;
        uint32_t so = sm32 + SWZ(row*128 + ch*16);
        size_t ga = base + (size_t)(qt*64 + row)*DD + ch*8;
        CP16(so + QH_O, Qh + ga);
        CP16(so + QL_O, Ql + ga);
    }
    auto load_kv = [&](int kt) {
        int stg = STG_O + (kt & 1) * STG_SZ;
        #pragma unroll
        for (int i = 0; i < 4; i++) {
            int idx = tid + i*128; int row = idx >> 3, ch = idx & 7;
            uint32_t so = sm32 + stg + SWZ(row*128 + ch*16);
            size_t ga = base + (size_t)(kt*64 + row)*DD + ch*8;
            CP16(so,        Kh + ga);
            CP16(so + 8192, Vh + ga);
        }
        CP_COMMIT();
    };
    load_kv(0);
    if (qt >= 1) load_kv(1);

    int lr = lane & 7;
    int a_r = lr + ((lane & 8) ? 8 : 0);
    int a_k = (lane & 16) ? 16 : 0;
    int b_r = lr + ((lane & 16) ? 8 : 0);
    int b_k = (lane & 8) ? 16 : 0;
    int v_r = lr + ((lane & 8) ? 8 : 0);
    int v_k = (lane & 16) ? 16 : 0;
    int wm = wid * 16;

    float o[8][4];
    #pragma unroll
    for (int nf = 0; nf < 8; nf++)
        #pragma unroll
        for (int j = 0; j < 4; j++) o[nf][j] = 0.f;
    float osum[4] = {0.f, 0.f, 0.f, 0.f};       // P x ones: row sums
    float mrow0 = -1e30f, mrow1 = -1e30f;

    if (qt >= 1) { CP_WAIT(1); } else { CP_WAIT(0); }
    __syncthreads();

    uint32_t qhf[4][4], qlf[4][4];
    #pragma unroll
    for (int kc = 0; kc < 4; kc++) {
        uint32_t off = SWZ((wm + a_r)*128 + kc*32 + a_k);
        LDSM_X4(qhf[kc][0], qhf[kc][1], qhf[kc][2], qhf[kc][3], sm32 + QH_O + off);
        LDSM_X4(qlf[kc][0], qlf[kc][1], qlf[kc][2], qlf[kc][3], sm32 + QL_O + off);
    }

    for (int kt = 0; kt <= qt; kt++) {
        if (kt > 0) {
            if (kt < qt) { CP_WAIT(1); } else { CP_WAIT(0); }
            __syncthreads();
        }
        uint32_t kbh = sm32 + STG_O + (kt & 1)*STG_SZ;
        uint32_t vbh = kbh + 8192;

        // ---- S = Q K^T (2-term fp16) ----
        float s[8][4];
        #pragma unroll
        for (int nf = 0; nf < 8; nf++)
            #pragma unroll
            for (int j = 0; j < 4; j++) s[nf][j] = 0.f;

        #pragma unroll
        for (int kc = 0; kc < 4; kc++) {
            #pragma unroll
            for (int c2 = 0; c2 < 4; c2++) {
                uint32_t h4[4];
                uint32_t off = SWZ((c2*16 + b_r)*128 + kc*32 + b_k);
                LDSM_X4(h4[0], h4[1], h4[2], h4[3], kbh + off);
                MMA_F16(s[c2*2],   qhf[kc], h4[0], h4[1]);
                MMA_F16(s[c2*2+1], qhf[kc], h4[2], h4[3]);
                MMA_F16(s[c2*2],   qlf[kc], h4[0], h4[1]);
                MMA_F16(s[c2*2+1], qlf[kc], h4[2], h4[3]);
            }
        }

        // ---- scale into log2 domain + causal mask ----
        #pragma unroll
        for (int nf = 0; nf < 8; nf++)
            #pragma unroll
            for (int j = 0; j < 4; j++) s[nf][j] *= SCALE_L2E;
        if (kt == qt) {
            int r0 = wm + (lane >> 2), r1 = r0 + 8;
            #pragma unroll
            for (int nf = 0; nf < 8; nf++) {
                int c = nf*8 + (lane & 3)*2;
                if (c   > r0) s[nf][0] = -1e30f;
                if (c+1 > r0) s[nf][1] = -1e30f;
                if (c   > r1) s[nf][2] = -1e30f;
                if (c+1 > r1) s[nf][3] = -1e30f;
            }
        }

        // ---- online softmax: max, then f16x2 exp2 ----
        float t0 = -1e30f, t1 = -1e30f;
        #pragma unroll
        for (int nf = 0; nf < 8; nf++) {
            t0 = fmaxf(t0, fmaxf(s[nf][0], s[nf][1]));
            t1 = fmaxf(t1, fmaxf(s[nf][2], s[nf][3]));
        }
        t0 = fmaxf(t0, __shfl_xor_sync(0xffffffffu, t0, 1));
        t0 = fmaxf(t0, __shfl_xor_sync(0xffffffffu, t0, 2));
        t1 = fmaxf(t1, __shfl_xor_sync(0xffffffffu, t1, 1));
        t1 = fmaxf(t1, __shfl_xor_sync(0xffffffffu, t1, 2));
        float mn0 = fmaxf(mrow0, t0), mn1 = fmaxf(mrow1, t1);
        float al0 = fexp2(mrow0 - mn0), al1 = fexp2(mrow1 - mn1);
        mrow0 = mn0; mrow1 = mn1;

        uint32_t p2[8][2];
        #pragma unroll
        for (int nf = 0; nf < 8; nf++) {
            p2[nf][0] = hexp2_2(pack_h2(s[nf][0] - mn0, s[nf][1] - mn0));
            p2[nf][1] = hexp2_2(pack_h2(s[nf][2] - mn1, s[nf][3] - mn1));
        }

        // ---- rescale accumulators ----
        #pragma unroll
        for (int nf = 0; nf < 8; nf++) {
            o[nf][0] *= al0; o[nf][1] *= al0;
            o[nf][2] *= al1; o[nf][3] *= al1;
        }
        osum[0] *= al0; osum[1] *= al0; osum[2] *= al1; osum[3] *= al1;

        // ---- O += P V (1-term) and row-sum MMA ----
        #pragma unroll
        for (int sk = 0; sk < 4; sk++) {
            uint32_t pha[4];
            pha[0] = p2[sk*2][0];   pha[1] = p2[sk*2][1];
            pha[2] = p2[sk*2+1][0]; pha[3] = p2[sk*2+1][1];
            MMA_F16(osum, pha, ONE2, ONE2);
            #pragma unroll
            for (int c2 = 0; c2 < 4; c2++) {
                uint32_t vh4[4];
                uint32_t off = SWZ((sk*16 + v_r)*128 + c2*32 + v_k);
                LDSM_X4T(vh4[0], vh4[1], vh4[2], vh4[3], vbh + off);
                MMA_F16(o[c2*2],   pha, vh4[0], vh4[1]);
                MMA_F16(o[c2*2+1], pha, vh4[2], vh4[3]);
            }
        }

        __syncthreads();
        if (kt + 2 <= qt) load_kv(kt + 2);
    }

    // ---- epilogue: O / rowsum, write f32 [B,T,C] ----
    float inv0 = 1.0f / osum[0], inv1 = 1.0f / osum[2];
    int r0 = qt*64 + wm + (lane >> 2), r1 = r0 + 8;
    size_t ob = (size_t)b * TT;
    #pragma unroll
    for (int nf = 0; nf < 8; nf++) {
        int d = nf*8 + (lane & 3)*2;
        float2 w0; w0.x = o[nf][0]*inv0; w0.y = o[nf][1]*inv0;
        float2 w1; w1.x = o[nf][2]*inv1; w1.y = o[nf][3]*inv1;
        *(float2*)(O + (ob + r0)*CC + h*DD + d) = w0;
        *(float2*)(O + (ob + r1)*CC + h*DD + d) = w1;
    }
}

#define ATTN_SMEM (1024 + 16384 + 2*16384)
#define MM_SMEM(NT) (1024 + 2*(32768 + (NT)*128))

// ===================== launch ===============================================
extern "C" void kernel_launch(void* const* d_in, const int* in_sizes, int n_in,
                              void* d_out, int out_size)
{
    const float* x    = (const float*)d_in[0];
    const float* ln1g = (const float*)d_in[1];
    const float* ln1b = (const float*)d_in[2];
    const float* wq   = (const float*)d_in[3];
    const float* wk   = (const float*)d_in[4];
    const float* wv   = (const float*)d_in[5];
    const float* ln2g = (const float*)d_in[6];
    const float* ln2b = (const float*)d_in[7];
    const float* wh   = (const float*)d_in[8];
    const float* bh   = (const float*)d_in[9];
    const float* wp   = (const float*)d_in[10];
    const float* bp   = (const float*)d_in[11];
    float* out = (float*)d_out;

    float *att, *x1;
    __half *hh, *hl, *h2h, *h2l, *hidh, *hidl;
    __half *qh, *ql, *kh, *vh;
    __half *wqh, *wkh, *wvh, *whh, *wph;
    cudaGetSymbolAddress((void**)&att,  g_att);
    cudaGetSymbolAddress((void**)&x1,   g_x1);
    cudaGetSymbolAddress((void**)&hh,   g_hh);
    cudaGetSymbolAddress((void**)&hl,   g_hl);
    cudaGetSymbolAddress((void**)&h2h,  g_h2h);
    cudaGetSymbolAddress((void**)&h2l,  g_h2l);
    cudaGetSymbolAddress((void**)&hidh, g_hidh);
    cudaGetSymbolAddress((void**)&hidl, g_hidl);
    cudaGetSymbolAddress((void**)&qh,   g_qh);
    cudaGetSymbolAddress((void**)&ql,   g_ql);
    cudaGetSymbolAddress((void**)&kh,   g_kh);
    cudaGetSymbolAddress((void**)&vh,   g_vh);
    cudaGetSymbolAddress((void**)&wqh,  g_wqh);
    cudaGetSymbolAddress((void**)&wkh,  g_wkh);
    cudaGetSymbolAddress((void**)&wvh,  g_wvh);
    cudaGetSymbolAddress((void**)&whh,  g_whh);
    cudaGetSymbolAddress((void**)&wph,  g_wph);

    cudaFuncSetAttribute(attn_kernel,
        cudaFuncAttributeMaxDynamicSharedMemorySize, ATTN_SMEM);
    cudaFuncSetAttribute(mm_kernel<64,3>,
        cudaFuncAttributeMaxDynamicSharedMemorySize, MM_SMEM(64));
    cudaFuncSetAttribute(mm_kernel<128,1>,
        cudaFuncAttributeMaxDynamicSharedMemorySize, MM_SMEM(128));
    cudaFuncSetAttribute(mm_kernel<128,2>,
        cudaFuncAttributeMaxDynamicSharedMemorySize, MM_SMEM(128));

    // weight prep: transpose + fp16 round
    tsplit_kernel<<<dim3(2, 24, HH), 256>>>(wq, wqh, CC, DD, (long)CC*DD);
    tsplit_kernel<<<dim3(2, 24, HH), 256>>>(wk, wkh, CC, DD, (long)CC*DD);
    tsplit_kernel<<<dim3(2, 24, HH), 256>>>(wv, wvh, CC, DD, (long)CC*DD);
    tsplit_kernel<<<dim3(96, 24, 1), 256>>>(wh, whh, CC, C4, 0);
    tsplit_kernel<<<dim3(24, 96, 1), 256>>>(wp, wph, C4, CC, 0);

    // LN1 -> split fp16
    ln_kernel<false><<<BT, 256>>>(x, x, ln1g, ln1b, hh, hl, nullptr);

    // fused QKV projection, out fp16 [B,H,T,D]
    QKVOut qkv;
    qkv.w0 = wqh; qkv.w1 = wkh; qkv.w2 = wvh;
    qkv.qh = qh; qkv.ql = ql; qkv.kh = kh; qkv.vh = vh;
    QKVOut qkv0 = {};
    mm_kernel<64,3><<<dim3(1, BT/128, 3*HH), 256, MM_SMEM(64)>>>(
        hh, hl, CC, 0, nullptr, 0,
        nullptr, 0, 0, CC, nullptr, nullptr, nullptr, nullptr, 0, qkv);

    // HMMA flash attention
    attn_kernel<<<dim3(TT/64, BB*HH), 128, ATTN_SMEM>>>(qh, ql, kh, vh, att);

    // residual + LN2 -> split fp16 (+x1)
    ln_kernel<true><<<BT, 256>>>(x, att, ln2g, ln2b, h2h, h2l, x1);

    // MLP (HMMA)
    mm_kernel<128,1><<<dim3(C4/128, BT/128, 1), 256, MM_SMEM(128)>>>(
        h2h, h2l, CC, 0, whh, 0, nullptr, 0, 0, CC, bh, nullptr,
        hidh, hidl, C4, qkv0);
    mm_kernel<128,2><<<dim3(CC/128, BT/128, 1), 256, MM_SMEM(128)>>>(
        hidh, hidl, C4, 0, wph, 0, out, CC, 0, C4, bp, x1,
        nullptr, nullptr, 0, qkv0);
}

// round 8
// speedup vs baseline: 7.7941x; 1.6152x over previous
#include <cuda_runtime.h>
#include <cuda_fp16.h>
#include <cstdint>

#define BB 2
#define TT 2048
#define CC 768
#define HH 12
#define DD 64
#define BT (BB*TT)          // 4096 rows
#define C4 (4*CC)           // 3072
#define SCALE 0.03608439182435161f           // 1/sqrt(768)
#define SCALE_L2E (0.03608439182435161f * 1.4426950408889634f)  // log2 domain

// ===================== PTX helpers (sm_80-compatible only) ==================
__device__ __forceinline__ uint32_t smem_u32(const void* p) {
    uint32_t a;
    asm("{ .reg .u64 t; cvta.to.shared.u64 t, %1; cvt.u32.u64 %0, t; }"
        : "=r"(a) : "l"(p));
    return a;
}

#define CP16(s, g) \
    asm volatile("cp.async.cg.shared.global [%0], [%1], 16;" :: "r"(s), "l"(g))
#define CP_COMMIT() asm volatile("cp.async.commit_group;" ::: "memory")
#define CP_WAIT(n)  asm volatile("cp.async.wait_group %0;" :: "n"(n) : "memory")

#define LDSM_X4(r0, r1, r2, r3, a) \
    asm volatile("ldmatrix.sync.aligned.m8n8.x4.shared.b16 {%0,%1,%2,%3}, [%4];" \
        : "=r"(r0), "=r"(r1), "=r"(r2), "=r"(r3) : "r"(a))

#define LDSM_X4T(r0, r1, r2, r3, a) \
    asm volatile("ldmatrix.sync.aligned.m8n8.x4.trans.shared.b16 {%0,%1,%2,%3}, [%4];" \
        : "=r"(r0), "=r"(r1), "=r"(r2), "=r"(r3) : "r"(a))

#define MMA_F16(d, a, b0, b1) \
    asm volatile("mma.sync.aligned.m16n8k16.row.col.f32.f16.f16.f32 " \
        "{%0,%1,%2,%3}, {%4,%5,%6,%7}, {%8,%9}, {%0,%1,%2,%3};" \
        : "+f"((d)[0]), "+f"((d)[1]), "+f"((d)[2]), "+f"((d)[3]) \
        : "r"((a)[0]), "r"((a)[1]), "r"((a)[2]), "r"((a)[3]), "r"(b0), "r"(b1))

#define SWZ(x) ((x) ^ (((x) >> 3) & 0x70))

__device__ __forceinline__ uint32_t pack_h2(float lo, float hi) {
    uint32_t r;
    asm("cvt.rn.f16x2.f32 %0, %1, %2;" : "=r"(r) : "f"(hi), "f"(lo));
    return r;
}
__device__ __forceinline__ uint32_t hexp2_2(uint32_t a) {
    uint32_t r;
    asm("ex2.approx.f16x2 %0, %1;" : "=r"(r) : "r"(a));
    return r;
}
__device__ __forceinline__ float fexp2(float x) {
    float r;
    asm("ex2.approx.ftz.f32 %0, %1;" : "=f"(r) : "f"(x));
    return r;
}

// ===================== scratch (static device memory) ======================
__device__ float g_att[BT*CC];
__device__ float g_x1 [BT*CC];
__device__ __half g_hh [BT*CC];
__device__ __half g_h2h[BT*CC];
__device__ __half g_hidh[(size_t)BT*C4];
// qkv, layout [B,H,T,D], fp16
__device__ __half g_qh[BT*CC];
__device__ __half g_kh[BT*CC];
__device__ __half g_vh[BT*CC];
__device__ __half g_wqh[HH*DD*CC];
__device__ __half g_wkh[HH*DD*CC];
__device__ __half g_wvh[HH*DD*CC];
__device__ __half g_whh[(size_t)C4*CC];
__device__ __half g_wph[(size_t)CC*C4];

struct QKVOut {
    const __half *w0, *w1, *w2;
    __half *qh, *kh, *vh;
};

// ===================== transpose + fp16 round for weights ==================
__global__ __launch_bounds__(256) void tsplit_kernel(
    const float* __restrict__ in, __half* __restrict__ oh,
    int R, int Cn, long strideZ)
{
    __shared__ float ts[32][33];
    size_t zo = (size_t)blockIdx.z * strideZ;
    int r0 = blockIdx.y * 32, c0 = blockIdx.x * 32;
    int tx = threadIdx.x & 31, ty = threadIdx.x >> 5;
    #pragma unroll
    for (int i = 0; i < 4; i++) {
        int r = r0 + ty + i*8;
        ts[ty + i*8][tx] = in[zo + (size_t)r*Cn + c0 + tx];
    }
    __syncthreads();
    #pragma unroll
    for (int i = 0; i < 4; i++) {
        int cc = ty + i*8;
        size_t oi = zo + (size_t)(c0 + cc)*R + r0 + tx;
        oh[oi] = __float2half(ts[tx][cc]);
    }
}

// ===================== LayerNorm -> fp16 (+opt residual) ===================
template<bool ADD>
__global__ __launch_bounds__(256) void ln_kernel(
    const float* __restrict__ x, const float* __restrict__ add,
    const float* __restrict__ g, const float* __restrict__ be,
    __half* __restrict__ oh, float* __restrict__ outsum)
{
    int row = blockIdx.x;
    int tid = threadIdx.x;
    const float* xr = x + (size_t)row*CC;
    const float* ar = add + (size_t)row*CC;
    float v[3]; float s = 0.f, sq = 0.f;
    #pragma unroll
    for (int i = 0; i < 3; i++) {
        int c = tid + i*256;
        float val = xr[c];
        if (ADD) val += ar[c];
        v[i] = val; s += val; sq = fmaf(val, val, sq);
    }
    #pragma unroll
    for (int o = 16; o > 0; o >>= 1) {
        s  += __shfl_down_sync(0xffffffffu, s,  o);
        sq += __shfl_down_sync(0xffffffffu, sq, o);
    }
    __shared__ float rs[8], rq[8], stat[2];
    if ((tid & 31) == 0) { rs[tid>>5] = s; rq[tid>>5] = sq; }
    __syncthreads();
    if (tid == 0) {
        float ts = 0.f, tq = 0.f;
        #pragma unroll
        for (int i = 0; i < 8; i++) { ts += rs[i]; tq += rq[i]; }
        float mu  = ts * (1.0f/CC);
        float var = tq * (1.0f/CC) - mu*mu;
        stat[0] = mu; stat[1] = rsqrtf(var + 1e-5f);
    }
    __syncthreads();
    float mu = stat[0], rstd = stat[1];
    #pragma unroll
    for (int i = 0; i < 3; i++) {
        int c = tid + i*256;
        float val = (v[i]-mu)*rstd*g[c] + be[c];
        oh[(size_t)row*CC + c] = __float2half(val);
        if (ADD) outsum[(size_t)row*CC + c] = v[i];
    }
}

// ===================== HMMA (mma.sync) GEMM =================================
// C[M,N] = A[M,K] * B[N,K]^T, fp16 1-term.
// MODE 1: +bias, ReLU, store fp16.  MODE 2: +bias +residual, f32 store.
// MODE 3: fused QKV (z = proj*HH + h), out fp16 [B,H,T,D].
template<int NT, int MODE>
__global__ __launch_bounds__(256)
void mm_kernel(
    const __half* __restrict__ Ah, int lda, long strideA,
    const __half* __restrict__ Bh, long strideB,
    float* __restrict__ C, int ldc, long strideC,
    int Ktot,
    const float* __restrict__ bias, const float* __restrict__ res,
    __half* __restrict__ Oh, int ldo,
    QKVOut qkv)
{
    static_assert(NT == 64 || NT == 128, "NT");
    constexpr int SA_H = 0;
    constexpr int SB_H = 16384;
    constexpr int STAGE = 16384 + NT*128;
    constexpr int NB = NT/32;
    constexpr int NW = NT/2;
    constexpr int NT8 = NW/8;
    constexpr int NT16 = NW/16;

    extern __shared__ char smraw[];
    char* sm = (char*)(((uintptr_t)smraw + 1023) & ~(uintptr_t)1023);
    uint32_t sm32 = smem_u32(sm);

    int tid = threadIdx.x;
    int wid = tid >> 5, lane = tid & 31;
    int z = blockIdx.z;
    int proj = 0, hsel = 0;
    if (MODE == 3) {
        proj = z / HH; hsel = z % HH;
        const __half* w = (proj == 0) ? qkv.w0 : (proj == 1) ? qkv.w1 : qkv.w2;
        Bh = w + (size_t)hsel*CC*DD;
    } else {
        Ah += (size_t)z * strideA;
        Bh += (size_t)z * strideB;
        if (MODE == 2) C += (size_t)z * strideC;
    }
    int bm = blockIdx.y * 128, bn = blockIdx.x * NT;

    int wm = (wid & 3) * 32;
    int wn = (wid >> 2) * NW;

    int lr = lane & 7;
    int a_r = lr + ((lane & 8) ? 8 : 0);
    int a_k = (lane & 16) ? 16 : 0;
    int b_r = lr + ((lane & 16) ? 8 : 0);
    int b_k = (lane & 8) ? 16 : 0;

    int g_row = tid >> 3, g_ch = tid & 7;

    float acc[2][NT8][4];
    #pragma unroll
    for (int mt = 0; mt < 2; mt++)
        #pragma unroll
        for (int nt = 0; nt < NT8; nt++)
            #pragma unroll
            for (int j = 0; j < 4; j++) acc[mt][nt][j] = 0.f;

    int nk = Ktot >> 6;

    auto load_stage = [&](int t) {
        int stg = (t & 1) * STAGE;
        int k0 = t << 6;
        #pragma unroll
        for (int i = 0; i < 4; i++) {
            int row = g_row + i*32;
            uint32_t so = sm32 + stg + SWZ(row*128 + g_ch*16);
            CP16(so + SA_H, Ah + (size_t)(bm+row)*lda + k0 + g_ch*8);
        }
        #pragma unroll
        for (int i = 0; i < NB; i++) {
            int row = g_row + i*32;
            uint32_t so = sm32 + stg + SWZ(row*128 + g_ch*16);
            CP16(so + SB_H, Bh + (size_t)(bn+row)*lda + k0 + g_ch*8);
        }
        CP_COMMIT();
    };

    load_stage(0);
    if (nk > 1) load_stage(1);

    for (int t = 0; t < nk; t++) {
        if (t < nk - 1) { CP_WAIT(1); } else { CP_WAIT(0); }
        __syncthreads();
        int stg = (t & 1) * STAGE;
        uint32_t baseA_h = sm32 + stg + SA_H;
        uint32_t baseB_h = sm32 + stg + SB_H;

        #pragma unroll
        for (int kt = 0; kt < 4; kt++) {
            int kb = kt*32;
            uint32_t ah[2][4];
            #pragma unroll
            for (int mt = 0; mt < 2; mt++) {
                uint32_t off = SWZ((wm + mt*16 + a_r)*128 + kb + a_k);
                LDSM_X4(ah[mt][0], ah[mt][1], ah[mt][2], ah[mt][3], baseA_h + off);
            }
            uint32_t bh[NT16][4];
            #pragma unroll
            for (int n2 = 0; n2 < NT16; n2++) {
                uint32_t off = SWZ((wn + n2*16 + b_r)*128 + kb + b_k);
                LDSM_X4(bh[n2][0], bh[n2][1], bh[n2][2], bh[n2][3], baseB_h + off);
            }
            #pragma unroll
            for (int mt = 0; mt < 2; mt++) {
                #pragma unroll
                for (int n2 = 0; n2 < NT16; n2++) {
                    MMA_F16(acc[mt][n2*2],   ah[mt], bh[n2][0], bh[n2][1]);
                    MMA_F16(acc[mt][n2*2+1], ah[mt], bh[n2][2], bh[n2][3]);
                }
            }
        }
        __syncthreads();
        if (t + 2 < nk) load_stage(t + 2);
    }

    // ---- epilogue ----
    int mrow0 = bm + wm + (lane >> 2);
    int ncol0 = bn + wn + (lane & 3) * 2;
    #pragma unroll
    for (int mt = 0; mt < 2; mt++) {
        #pragma unroll
        for (int half = 0; half < 2; half++) {
            int m = mrow0 + mt*16 + half*8;
            #pragma unroll
            for (int nt = 0; nt < NT8; nt++) {
                int n = ncol0 + nt*8;
                float v0 = acc[mt][nt][half*2];
                float v1 = acc[mt][nt][half*2+1];
                if (MODE == 1) {
                    v0 = fmaxf(v0 + bias[n],   0.f);
                    v1 = fmaxf(v1 + bias[n+1], 0.f);
                    __half2 hh2;
                    hh2.x = __float2half(v0); hh2.y = __float2half(v1);
                    *(__half2*)(Oh + (size_t)m*ldo + n) = hh2;
                } else if (MODE == 2) {
                    float2 rr = *(const float2*)(res + (size_t)m*ldc + n);
                    float2 o;
                    o.x = v0 + bias[n]   + rr.x;
                    o.y = v1 + bias[n+1] + rr.y;
                    *(float2*)(C + (size_t)m*ldc + n) = o;
                } else if (MODE == 3) {
                    int bidx = m >> 11, tt = m & (TT-1);
                    size_t o = (((size_t)bidx*HH + hsel)*TT + tt)*DD + n;
                    __half2 hh2;
                    hh2.x = __float2half(v0); hh2.y = __float2half(v1);
                    __half* p = (proj == 0) ? qkv.qh : (proj == 1) ? qkv.kh : qkv.vh;
                    *(__half2*)(p + o) = hh2;
                }
            }
        }
    }
}

// ===================== HMMA flash attention (causal) ========================
// 128 threads (4 warps), warp owns 16 q rows. fp16 1-term throughout.
// Softmax in log2 domain with f16x2 ex2; P = fp16 A-frags directly.
// Row sums via all-ones B-fragment MMA.
__global__ __launch_bounds__(128) void attn_kernel(
    const __half* __restrict__ Qh, const __half* __restrict__ Kh,
    const __half* __restrict__ Vh, float* __restrict__ O)
{
    extern __shared__ char smraw[];
    char* sm = (char*)(((uintptr_t)smraw + 1023) & ~(uintptr_t)1023);
    uint32_t sm32 = smem_u32(sm);

    constexpr int QH_O = 0, STG_O = 8192, STG_SZ = 16384;
    constexpr uint32_t ONE2 = 0x3C003C00u;   // half2(1.0, 1.0)

    int qt = gridDim.x - 1 - (int)blockIdx.x;   // longest first
    int bh = blockIdx.y;
    int b = bh / HH, h = bh % HH;
    int tid = threadIdx.x, wid = tid >> 5, lane = tid & 31;
    size_t base = (size_t)bh * TT * DD;

    // ---- Q tile: 64 rows x 128B = 512 chunks = 128 thr x 4 iters (ALL) ----
    #pragma unroll
    for (int i = 0; i < 4; i++) {
        int idx = tid + i*128; int row = idx >> 3, ch = idx & 7;
        uint32_t so = sm32 + SWZ(row*128 + ch*16);
        size_t ga = base + (size_t)(qt*64 + row)*DD + ch*8;
        CP16(so + QH_O, Qh + ga);
    }
    auto load_kv = [&](int kt) {
        int stg = STG_O + (kt & 1) * STG_SZ;
        #pragma unroll
        for (int i = 0; i < 4; i++) {
            int idx = tid + i*128; int row = idx >> 3, ch = idx & 7;
            uint32_t so = sm32 + stg + SWZ(row*128 + ch*16);
            size_t ga = base + (size_t)(kt*64 + row)*DD + ch*8;
            CP16(so,        Kh + ga);
            CP16(so + 8192, Vh + ga);
        }
        CP_COMMIT();
    };
    load_kv(0);
    if (qt >= 1) load_kv(1);

    int lr = lane & 7;
    int a_r = lr + ((lane & 8) ? 8 : 0);
    int a_k = (lane & 16) ? 16 : 0;
    int b_r = lr + ((lane & 16) ? 8 : 0);
    int b_k = (lane & 8) ? 16 : 0;
    int v_r = lr + ((lane & 8) ? 8 : 0);
    int v_k = (lane & 16) ? 16 : 0;
    int wm = wid * 16;

    float o[8][4];
    #pragma unroll
    for (int nf = 0; nf < 8; nf++)
        #pragma unroll
        for (int j = 0; j < 4; j++) o[nf][j] = 0.f;
    float osum[4] = {0.f, 0.f, 0.f, 0.f};
    float mrow0 = -1e30f, mrow1 = -1e30f;

    if (qt >= 1) { CP_WAIT(1); } else { CP_WAIT(0); }
    __syncthreads();

    uint32_t qhf[4][4];
    #pragma unroll
    for (int kc = 0; kc < 4; kc++) {
        uint32_t off = SWZ((wm + a_r)*128 + kc*32 + a_k);
        LDSM_X4(qhf[kc][0], qhf[kc][1], qhf[kc][2], qhf[kc][3], sm32 + QH_O + off);
    }

    for (int kt = 0; kt <= qt; kt++) {
        if (kt > 0) {
            if (kt < qt) { CP_WAIT(1); } else { CP_WAIT(0); }
            __syncthreads();
        }
        uint32_t kbh = sm32 + STG_O + (kt & 1)*STG_SZ;
        uint32_t vbh = kbh + 8192;

        // ---- S = Q K^T (1-term fp16) ----
        float s[8][4];
        #pragma unroll
        for (int nf = 0; nf < 8; nf++)
            #pragma unroll
            for (int j = 0; j < 4; j++) s[nf][j] = 0.f;

        #pragma unroll
        for (int kc = 0; kc < 4; kc++) {
            #pragma unroll
            for (int c2 = 0; c2 < 4; c2++) {
                uint32_t h4[4];
                uint32_t off = SWZ((c2*16 + b_r)*128 + kc*32 + b_k);
                LDSM_X4(h4[0], h4[1], h4[2], h4[3], kbh + off);
                MMA_F16(s[c2*2],   qhf[kc], h4[0], h4[1]);
                MMA_F16(s[c2*2+1], qhf[kc], h4[2], h4[3]);
            }
        }

        // ---- scale into log2 domain + causal mask ----
        #pragma unroll
        for (int nf = 0; nf < 8; nf++)
            #pragma unroll
            for (int j = 0; j < 4; j++) s[nf][j] *= SCALE_L2E;
        if (kt == qt) {
            int r0 = wm + (lane >> 2), r1 = r0 + 8;
            #pragma unroll
            for (int nf = 0; nf < 8; nf++) {
                int c = nf*8 + (lane & 3)*2;
                if (c   > r0) s[nf][0] = -1e30f;
                if (c+1 > r0) s[nf][1] = -1e30f;
                if (c   > r1) s[nf][2] = -1e30f;
                if (c+1 > r1) s[nf][3] = -1e30f;
            }
        }

        // ---- online softmax: max, then f16x2 exp2 ----
        float t0 = -1e30f, t1 = -1e30f;
        #pragma unroll
        for (int nf = 0; nf < 8; nf++) {
            t0 = fmaxf(t0, fmaxf(s[nf][0], s[nf][1]));
            t1 = fmaxf(t1, fmaxf(s[nf][2], s[nf][3]));
        }
        t0 = fmaxf(t0, __shfl_xor_sync(0xffffffffu, t0, 1));
        t0 = fmaxf(t0, __shfl_xor_sync(0xffffffffu, t0, 2));
        t1 = fmaxf(t1, __shfl_xor_sync(0xffffffffu, t1, 1));
        t1 = fmaxf(t1, __shfl_xor_sync(0xffffffffu, t1, 2));
        float mn0 = fmaxf(mrow0, t0), mn1 = fmaxf(mrow1, t1);
        float al0 = fexp2(mrow0 - mn0), al1 = fexp2(mrow1 - mn1);
        mrow0 = mn0; mrow1 = mn1;

        uint32_t p2[8][2];
        #pragma unroll
        for (int nf = 0; nf < 8; nf++) {
            p2[nf][0] = hexp2_2(pack_h2(s[nf][0] - mn0, s[nf][1] - mn0));
            p2[nf][1] = hexp2_2(pack_h2(s[nf][2] - mn1, s[nf][3] - mn1));
        }

        // ---- rescale accumulators ----
        #pragma unroll
        for (int nf = 0; nf < 8; nf++) {
            o[nf][0] *= al0; o[nf][1] *= al0;
            o[nf][2] *= al1; o[nf][3] *= al1;
        }
        osum[0] *= al0; osum[1] *= al0; osum[2] *= al1; osum[3] *= al1;

        // ---- O += P V and row-sum MMA ----
        #pragma unroll
        for (int sk = 0; sk < 4; sk++) {
            uint32_t pha[4];
            pha[0] = p2[sk*2][0];   pha[1] = p2[sk*2][1];
            pha[2] = p2[sk*2+1][0]; pha[3] = p2[sk*2+1][1];
            MMA_F16(osum, pha, ONE2, ONE2);
            #pragma unroll
            for (int c2 = 0; c2 < 4; c2++) {
                uint32_t vh4[4];
                uint32_t off = SWZ((sk*16 + v_r)*128 + c2*32 + v_k);
                LDSM_X4T(vh4[0], vh4[1], vh4[2], vh4[3], vbh + off);
                MMA_F16(o[c2*2],   pha, vh4[0], vh4[1]);
                MMA_F16(o[c2*2+1], pha, vh4[2], vh4[3]);
            }
        }

        __syncthreads();
        if (kt + 2 <= qt) load_kv(kt + 2);
    }

    // ---- epilogue: O / rowsum, write f32 [B,T,C] ----
    float inv0 = 1.0f / osum[0], inv1 = 1.0f / osum[2];
    int r0 = qt*64 + wm + (lane >> 2), r1 = r0 + 8;
    size_t ob = (size_t)b * TT;
    #pragma unroll
    for (int nf = 0; nf < 8; nf++) {
        int d = nf*8 + (lane & 3)*2;
        float2 w0; w0.x = o[nf][0]*inv0; w0.y = o[nf][1]*inv0;
        float2 w1; w1.x = o[nf][2]*inv1; w1.y = o[nf][3]*inv1;
        *(float2*)(O + (ob + r0)*CC + h*DD + d) = w0;
        *(float2*)(O + (ob + r1)*CC + h*DD + d) = w1;
    }
}

#define ATTN_SMEM (1024 + 8192 + 2*16384)
#define MM_SMEM(NT) (1024 + 2*(16384 + (NT)*128))

// ===================== launch ===============================================
extern "C" void kernel_launch(void* const* d_in, const int* in_sizes, int n_in,
                              void* d_out, int out_size)
{
    const float* x    = (const float*)d_in[0];
    const float* ln1g = (const float*)d_in[1];
    const float* ln1b = (const float*)d_in[2];
    const float* wq   = (const float*)d_in[3];
    const float* wk   = (const float*)d_in[4];
    const float* wv   = (const float*)d_in[5];
    const float* ln2g = (const float*)d_in[6];
    const float* ln2b = (const float*)d_in[7];
    const float* wh   = (const float*)d_in[8];
    const float* bh   = (const float*)d_in[9];
    const float* wp   = (const float*)d_in[10];
    const float* bp   = (const float*)d_in[11];
    float* out = (float*)d_out;

    float *att, *x1;
    __half *hh, *h2h, *hidh;
    __half *qh, *kh, *vh;
    __half *wqh, *wkh, *wvh, *whh, *wph;
    cudaGetSymbolAddress((void**)&att,  g_att);
    cudaGetSymbolAddress((void**)&x1,   g_x1);
    cudaGetSymbolAddress((void**)&hh,   g_hh);
    cudaGetSymbolAddress((void**)&h2h,  g_h2h);
    cudaGetSymbolAddress((void**)&hidh, g_hidh);
    cudaGetSymbolAddress((void**)&qh,   g_qh);
    cudaGetSymbolAddress((void**)&kh,   g_kh);
    cudaGetSymbolAddress((void**)&vh,   g_vh);
    cudaGetSymbolAddress((void**)&wqh,  g_wqh);
    cudaGetSymbolAddress((void**)&wkh,  g_wkh);
    cudaGetSymbolAddress((void**)&wvh,  g_wvh);
    cudaGetSymbolAddress((void**)&whh,  g_whh);
    cudaGetSymbolAddress((void**)&wph,  g_wph);

    cudaFuncSetAttribute(attn_kernel,
        cudaFuncAttributeMaxDynamicSharedMemorySize, ATTN_SMEM);
    cudaFuncSetAttribute(mm_kernel<64,3>,
        cudaFuncAttributeMaxDynamicSharedMemorySize, MM_SMEM(64));
    cudaFuncSetAttribute(mm_kernel<128,1>,
        cudaFuncAttributeMaxDynamicSharedMemorySize, MM_SMEM(128));
    cudaFuncSetAttribute(mm_kernel<128,2>,
        cudaFuncAttributeMaxDynamicSharedMemorySize, MM_SMEM(128));

    // weight prep: transpose + fp16 round
    tsplit_kernel<<<dim3(2, 24, HH), 256>>>(wq, wqh, CC, DD, (long)CC*DD);
    tsplit_kernel<<<dim3(2, 24, HH), 256>>>(wk, wkh, CC, DD, (long)CC*DD);
    tsplit_kernel<<<dim3(2, 24, HH), 256>>>(wv, wvh, CC, DD, (long)CC*DD);
    tsplit_kernel<<<dim3(96, 24, 1), 256>>>(wh, whh, CC, C4, 0);
    tsplit_kernel<<<dim3(24, 96, 1), 256>>>(wp, wph, C4, CC, 0);

    // LN1 -> fp16
    ln_kernel<false><<<BT, 256>>>(x, x, ln1g, ln1b, hh, nullptr);

    // fused QKV projection, out fp16 [B,H,T,D]
    QKVOut qkv;
    qkv.w0 = wqh; qkv.w1 = wkh; qkv.w2 = wvh;
    qkv.qh = qh; qkv.kh = kh; qkv.vh = vh;
    QKVOut qkv0 = {};
    mm_kernel<64,3><<<dim3(1, BT/128, 3*HH), 256, MM_SMEM(64)>>>(
        hh, CC, 0, nullptr, 0,
        nullptr, 0, 0, CC, nullptr, nullptr, nullptr, 0, qkv);

    // HMMA flash attention
    attn_kernel<<<dim3(TT/64, BB*HH), 128, ATTN_SMEM>>>(qh, kh, vh, att);

    // residual + LN2 -> fp16 (+x1)
    ln_kernel<true><<<BT, 256>>>(x, att, ln2g, ln2b, h2h, x1);

    // MLP (HMMA)
    mm_kernel<128,1><<<dim3(C4/128, BT/128, 1), 256, MM_SMEM(128)>>>(
        h2h, CC, 0, whh, 0, nullptr, 0, 0, CC, bh, nullptr,
        hidh, C4, qkv0);
    mm_kernel<128,2><<<dim3(CC/128, BT/128, 1), 256, MM_SMEM(128)>>>(
        hidh, C4, 0, wph, 0, out, CC, 0, C4, bp, x1,
        nullptr, 0, qkv0);
}